// round 1
// baseline (speedup 1.0000x reference)
#include <cuda_runtime.h>
#include <math.h>

// Problem constants
#define BATCH 16
#define CCH   256          // channels
#define NPOS  4096         // 64*64 spatial
#define HEADS 4
#define DHEAD 32
#define INNER 128          // HEADS*DHEAD
#define OC3   384          // 3*INNER
#define SCALEQ 0.17677669529663687f   // 32^-0.5
#define EPSV  1e-5f
#define NSPLIT 8

// ---------------- scratch (static device globals: alloc-free rule) ----------
__device__ float g_qkv[(size_t)BATCH * OC3 * NPOS];          // ~100 MB
__device__ float g_y[(size_t)BATCH * CCH * NPOS];            // ~67 MB
__device__ float g_kmax[BATCH * INNER];
__device__ float g_kinv[BATCH * INNER];
__device__ float g_ctxp[(size_t)BATCH * HEADS * NSPLIT * DHEAD * DHEAD];
__device__ float g_ctx[(size_t)BATCH * HEADS * DHEAD * DHEAD];
__device__ float g_part[BATCH * 128 * 2];                    // per-tile sum / sumsq
__device__ float g_mean[BATCH];
__device__ float g_rstd[BATCH];

// ---------------------------------------------------------------------------
// K1: qkv[b][o][p] = sum_c w_qkv[o][c] * x[b][c][p]
// Tile: 128(M) x 64(N) x 16(K), 256 threads, 8x4 per thread.
// ---------------------------------------------------------------------------
__global__ __launch_bounds__(256) void k_qkv_gemm(const float* __restrict__ x,
                                                  const float* __restrict__ w) {
    __shared__ float As[16 * 128];   // [k][m]
    __shared__ float Bs[16 * 64];    // [k][n]
    const int b    = blockIdx.z;
    const int row0 = blockIdx.y * 128;
    const int col0 = blockIdx.x * 64;
    const float* Xb = x + (size_t)b * CCH * NPOS;
    const int t  = threadIdx.x;
    const int ty = t >> 4;          // 0..15 -> o = ty*8
    const int tx = t & 15;          // 0..15 -> p = tx*4
    float acc[8][4];
#pragma unroll
    for (int i = 0; i < 8; i++)
#pragma unroll
        for (int j = 0; j < 4; j++) acc[i][j] = 0.f;

    const int ao = t >> 1;              // 0..127
    const int ac = (t & 1) * 8;         // 0 or 8
    const int bc = t >> 4;              // 0..15
    const int bp = (t & 15) * 4;        // 0..60

    for (int k0 = 0; k0 < CCH; k0 += 16) {
        // A tile (transpose-store)
        const float* wp = w + (size_t)(row0 + ao) * CCH + k0 + ac;
        float4 w0 = *(const float4*)wp;
        float4 w1 = *(const float4*)(wp + 4);
        As[(ac + 0) * 128 + ao] = w0.x; As[(ac + 1) * 128 + ao] = w0.y;
        As[(ac + 2) * 128 + ao] = w0.z; As[(ac + 3) * 128 + ao] = w0.w;
        As[(ac + 4) * 128 + ao] = w1.x; As[(ac + 5) * 128 + ao] = w1.y;
        As[(ac + 6) * 128 + ao] = w1.z; As[(ac + 7) * 128 + ao] = w1.w;
        // B tile
        *(float4*)&Bs[bc * 64 + bp] =
            *(const float4*)&Xb[(size_t)(k0 + bc) * NPOS + col0 + bp];
        __syncthreads();
#pragma unroll
        for (int kk = 0; kk < 16; kk++) {
            float4 a0 = *(float4*)&As[kk * 128 + ty * 8];
            float4 a1 = *(float4*)&As[kk * 128 + ty * 8 + 4];
            float4 bv = *(float4*)&Bs[kk * 64 + tx * 4];
            float av[8] = {a0.x, a0.y, a0.z, a0.w, a1.x, a1.y, a1.z, a1.w};
            float bb[4] = {bv.x, bv.y, bv.z, bv.w};
#pragma unroll
            for (int i = 0; i < 8; i++)
#pragma unroll
                for (int j = 0; j < 4; j++) acc[i][j] += av[i] * bb[j];
        }
        __syncthreads();
    }
    float* outp = g_qkv + (size_t)b * OC3 * NPOS;
#pragma unroll
    for (int i = 0; i < 8; i++) {
        float4 v = make_float4(acc[i][0], acc[i][1], acc[i][2], acc[i][3]);
        *(float4*)&outp[(size_t)(row0 + ty * 8 + i) * NPOS + col0 + tx * 4] = v;
    }
}

// ---------------------------------------------------------------------------
// K2: per (b, k-channel) row: max and 1/sum(exp) over n (single global pass)
// ---------------------------------------------------------------------------
__global__ __launch_bounds__(256) void k_kstats() {
    const int row = blockIdx.x;              // 0 .. B*INNER-1
    const int b = row >> 7, kc = row & 127;
    const float* kr = g_qkv + ((size_t)b * OC3 + INNER + kc) * NPOS;
    const int t = threadIdx.x;
    float v[16];
    float m = -1e30f;
#pragma unroll
    for (int i = 0; i < 16; i++) { v[i] = kr[i * 256 + t]; m = fmaxf(m, v[i]); }
    __shared__ float red[8];
#pragma unroll
    for (int o = 16; o > 0; o >>= 1) m = fmaxf(m, __shfl_xor_sync(0xffffffffu, m, o));
    if ((t & 31) == 0) red[t >> 5] = m;
    __syncthreads();
    if (t < 32) {
        float mm = (t < 8) ? red[t] : -1e30f;
#pragma unroll
        for (int o = 16; o > 0; o >>= 1) mm = fmaxf(mm, __shfl_xor_sync(0xffffffffu, mm, o));
        if (t == 0) red[0] = mm;
    }
    __syncthreads();
    m = red[0];
    __syncthreads();
    float s = 0.f;
#pragma unroll
    for (int i = 0; i < 16; i++) s += __expf(v[i] - m);
#pragma unroll
    for (int o = 16; o > 0; o >>= 1) s += __shfl_xor_sync(0xffffffffu, s, o);
    if ((t & 31) == 0) red[t >> 5] = s;
    __syncthreads();
    if (t == 0) {
        float ss = 0.f;
        for (int i = 0; i < 8; i++) ss += red[i];
        g_kmax[row] = m;
        g_kinv[row] = 1.0f / ss;
    }
}

// ---------------------------------------------------------------------------
// K3: split-K context partials: ctxp[b,h,s,d,e] = sum_{n in slice} softk[d,n]*v[e,n]
// ---------------------------------------------------------------------------
__global__ __launch_bounds__(256) void k_context() {
    const int s = blockIdx.x, h = blockIdx.y, b = blockIdx.z;
    __shared__ float ks[32 * 129];
    __shared__ float vs[32 * 129];
    __shared__ float smax[32], sinv[32];
    const int t = threadIdx.x;
    const int e = t & 31, dg = t >> 5;   // dg 0..7 -> d = dg*4 + i
    float acc[4] = {0.f, 0.f, 0.f, 0.f};
    const float* kbase = g_qkv + ((size_t)b * OC3 + INNER + h * DHEAD) * NPOS;
    const float* vbase = g_qkv + ((size_t)b * OC3 + 2 * INNER + h * DHEAD) * NPOS;
    if (t < 32) {
        smax[t] = g_kmax[b * INNER + h * DHEAD + t];
        sinv[t] = g_kinv[b * INNER + h * DHEAD + t];
    }
    __syncthreads();
    for (int tile = 0; tile < 4; tile++) {
        const int n0 = s * 512 + tile * 128;
#pragma unroll
        for (int i = 0; i < 16; i++) {
            int idx = i * 256 + t;
            int d = idx >> 7, nn = idx & 127;
            float kraw = kbase[(size_t)d * NPOS + n0 + nn];
            ks[d * 129 + nn] = __expf(kraw - smax[d]) * sinv[d];
            vs[d * 129 + nn] = vbase[(size_t)d * NPOS + n0 + nn];
        }
        __syncthreads();
        for (int nn = 0; nn < 128; nn++) {
            float vv = vs[e * 129 + nn];
#pragma unroll
            for (int i = 0; i < 4; i++) acc[i] += ks[(dg * 4 + i) * 129 + nn] * vv;
        }
        __syncthreads();
    }
    float* cp = g_ctxp + ((size_t)(b * HEADS + h) * NSPLIT + s) * 1024;
#pragma unroll
    for (int i = 0; i < 4; i++) cp[(dg * 4 + i) * 32 + e] = acc[i];
}

__global__ void k_ctx_reduce() {
    const int idx = blockIdx.x * 256 + threadIdx.x;   // 65536 total
    const int bh = idx >> 10, de = idx & 1023;
    float s = 0.f;
#pragma unroll
    for (int j = 0; j < NSPLIT; j++)
        s += g_ctxp[((size_t)bh * NSPLIT + j) * 1024 + de];
    g_ctx[(size_t)bh * 1024 + de] = s;
}

// ---------------------------------------------------------------------------
// K4: fused  q-softmax(d) -> inner = ctx^T * softq -> y = w_out*inner + b_out
//     plus deterministic per-tile sum/sumsq partials for GroupNorm.
// One block per (b, 32-column tile). smem = 48 KB exactly.
// ---------------------------------------------------------------------------
__global__ __launch_bounds__(256) void k_attn_out(const float* __restrict__ wout,
                                                  const float* __restrict__ bout) {
    __shared__ float sq[128 * 32];       // q channels [c][p]
    __shared__ float inner_s[128 * 32];  // [e][p]
    __shared__ float cbuf[4096];         // ctx, then w_out chunks
    const int tile = blockIdx.x, b = blockIdx.y;
    const int col0 = tile * 32;
    const int t = threadIdx.x;
    const float* qbase = g_qkv + (size_t)b * OC3 * NPOS;

    // load q tile + ctx
#pragma unroll
    for (int i = 0; i < 16; i++) {
        int idx = i * 256 + t;
        int c = idx >> 5, p = idx & 31;
        sq[c * 32 + p] = qbase[(size_t)c * NPOS + col0 + p];
    }
#pragma unroll
    for (int i = 0; i < 16; i++)
        cbuf[i * 256 + t] = g_ctx[(size_t)b * 4096 + i * 256 + t];
    __syncthreads();

    // softmax over d per (h, p) column, * SCALE
    if (t < 128) {
        const int h = t >> 5, p = t & 31;
        float m = -1e30f;
#pragma unroll
        for (int d = 0; d < 32; d++) m = fmaxf(m, sq[(h * 32 + d) * 32 + p]);
        float ssum = 0.f;
#pragma unroll
        for (int d = 0; d < 32; d++) ssum += __expf(sq[(h * 32 + d) * 32 + p] - m);
        const float inv = SCALEQ / ssum;
#pragma unroll
        for (int d = 0; d < 32; d++)
            sq[(h * 32 + d) * 32 + p] = __expf(sq[(h * 32 + d) * 32 + p] - m) * inv;
    }
    __syncthreads();

    // stage 2: inner[e][p] = sum_d ctx[h][d][e] * softq[h*32+d][p]
    {
        const int p = t & 31, eg = t >> 5;       // eg 0..7
        const int h = eg >> 1;
        const int e0 = (eg & 1) * 16;
        float sqv[32];
#pragma unroll
        for (int d = 0; d < 32; d++) sqv[d] = sq[(h * 32 + d) * 32 + p];
        float acc2[16];
#pragma unroll
        for (int i = 0; i < 16; i++) acc2[i] = 0.f;
#pragma unroll
        for (int d = 0; d < 32; d++) {
            const float qd = sqv[d];
#pragma unroll
            for (int i4 = 0; i4 < 4; i4++) {
                float4 c4 = *(float4*)&cbuf[h * 1024 + d * 32 + e0 + i4 * 4];
                acc2[i4 * 4 + 0] += c4.x * qd;
                acc2[i4 * 4 + 1] += c4.y * qd;
                acc2[i4 * 4 + 2] += c4.z * qd;
                acc2[i4 * 4 + 3] += c4.w * qd;
            }
        }
#pragma unroll
        for (int i = 0; i < 16; i++)
            inner_s[(h * 32 + e0 + i) * 32 + p] = acc2[i];
    }
    __syncthreads();

    // stage 3: y[o][p] = sum_e w_out[o][e]*inner[e][p]; w chunks staged in cbuf
    const int ty = t >> 3, tx = t & 7;           // o = ty*8.., p = tx*4..
    float acc3[8][4];
#pragma unroll
    for (int i = 0; i < 8; i++)
#pragma unroll
        for (int j = 0; j < 4; j++) acc3[i][j] = 0.f;

    for (int et = 0; et < 8; et++) {
        {   // load w chunk transposed: cbuf[e'][o], 16 x 256
            const int o = t;
#pragma unroll
            for (int q = 0; q < 4; q++) {
                float4 wv = *(const float4*)&wout[(size_t)o * INNER + et * 16 + q * 4];
                cbuf[(q * 4 + 0) * 256 + o] = wv.x;
                cbuf[(q * 4 + 1) * 256 + o] = wv.y;
                cbuf[(q * 4 + 2) * 256 + o] = wv.z;
                cbuf[(q * 4 + 3) * 256 + o] = wv.w;
            }
        }
        __syncthreads();
#pragma unroll
        for (int ee = 0; ee < 16; ee++) {
            float4 a0 = *(float4*)&cbuf[ee * 256 + ty * 8];
            float4 a1 = *(float4*)&cbuf[ee * 256 + ty * 8 + 4];
            float4 bv = *(float4*)&inner_s[(et * 16 + ee) * 32 + tx * 4];
            float av[8] = {a0.x, a0.y, a0.z, a0.w, a1.x, a1.y, a1.z, a1.w};
            float bb[4] = {bv.x, bv.y, bv.z, bv.w};
#pragma unroll
            for (int i = 0; i < 8; i++)
#pragma unroll
                for (int j = 0; j < 4; j++) acc3[i][j] += av[i] * bb[j];
        }
        __syncthreads();
    }

    // bias + write + partial sums (reuse sq space for reduction scratch)
    float lsum = 0.f, lsq = 0.f;
    float* yb = g_y + (size_t)b * CCH * NPOS;
#pragma unroll
    for (int i = 0; i < 8; i++) {
        const int o = ty * 8 + i;
        const float bo = bout[o];
        float4 v = make_float4(acc3[i][0] + bo, acc3[i][1] + bo,
                               acc3[i][2] + bo, acc3[i][3] + bo);
        *(float4*)&yb[(size_t)o * NPOS + col0 + tx * 4] = v;
        lsum += v.x + v.y + v.z + v.w;
        lsq  += v.x * v.x + v.y * v.y + v.z * v.z + v.w * v.w;
    }
    float* rs = sq;        // sq is dead now
    float* rq = sq + 8;
#pragma unroll
    for (int o = 16; o > 0; o >>= 1) {
        lsum += __shfl_xor_sync(0xffffffffu, lsum, o);
        lsq  += __shfl_xor_sync(0xffffffffu, lsq, o);
    }
    if ((t & 31) == 0) { rs[t >> 5] = lsum; rq[t >> 5] = lsq; }
    __syncthreads();
    if (t == 0) {
        float a = 0.f, q = 0.f;
        for (int i = 0; i < 8; i++) { a += rs[i]; q += rq[i]; }
        g_part[(b * 128 + tile) * 2 + 0] = a;
        g_part[(b * 128 + tile) * 2 + 1] = q;
    }
}

// ---------------------------------------------------------------------------
// K5: combine partials per batch (double precision)
// ---------------------------------------------------------------------------
__global__ void k_gn_stats() {
    const int b = blockIdx.x;
    const int t = threadIdx.x;    // 128
    double s = (double)g_part[(b * 128 + t) * 2 + 0];
    double q = (double)g_part[(b * 128 + t) * 2 + 1];
#pragma unroll
    for (int o = 16; o > 0; o >>= 1) {
        s += __shfl_xor_sync(0xffffffffu, s, o);
        q += __shfl_xor_sync(0xffffffffu, q, o);
    }
    __shared__ double ss[4], qq[4];
    if ((t & 31) == 0) { ss[t >> 5] = s; qq[t >> 5] = q; }
    __syncthreads();
    if (t == 0) {
        double S = 0.0, Q = 0.0;
        for (int i = 0; i < 4; i++) { S += ss[i]; Q += qq[i]; }
        const double cnt = (double)CCH * (double)NPOS;
        const double mean = S / cnt;
        const double var = Q / cnt - mean * mean;
        g_mean[b] = (float)mean;
        g_rstd[b] = (float)(1.0 / sqrt(var + (double)EPSV));
    }
}

// ---------------------------------------------------------------------------
// K6: normalize + gamma/beta
// ---------------------------------------------------------------------------
__global__ __launch_bounds__(256) void k_norm(float* __restrict__ out,
                                              const float* __restrict__ gamma,
                                              const float* __restrict__ beta) {
    const size_t idx4 = (size_t)blockIdx.x * 256 + threadIdx.x;
    const size_t base = idx4 * 4;
    const int b = (int)(base / ((size_t)CCH * NPOS));
    const int c = (int)(base / NPOS) & 255;
    const float mean = g_mean[b], rstd = g_rstd[b];
    const float g = gamma[c] * rstd, bt = beta[c];
    float4 v = *(float4*)&g_y[base];
    v.x = (v.x - mean) * g + bt;
    v.y = (v.y - mean) * g + bt;
    v.z = (v.z - mean) * g + bt;
    v.w = (v.w - mean) * g + bt;
    *(float4*)&out[base] = v;
}

// ---------------------------------------------------------------------------
extern "C" void kernel_launch(void* const* d_in, const int* in_sizes, int n_in,
                              void* d_out, int out_size) {
    const float* x     = (const float*)d_in[0];
    const float* wqkv  = (const float*)d_in[1];
    const float* wout  = (const float*)d_in[2];
    const float* bout  = (const float*)d_in[3];
    const float* gamma = (const float*)d_in[4];
    const float* beta  = (const float*)d_in[5];
    float* out = (float*)d_out;

    k_qkv_gemm <<<dim3(NPOS / 64, OC3 / 128, BATCH), 256>>>(x, wqkv);
    k_kstats   <<<BATCH * INNER, 256>>>();
    k_context  <<<dim3(NSPLIT, HEADS, BATCH), 256>>>();
    k_ctx_reduce<<<(BATCH * HEADS * DHEAD * DHEAD) / 256, 256>>>();
    k_attn_out <<<dim3(NPOS / 32, BATCH), 256>>>(wout, bout);
    k_gn_stats <<<BATCH, 128>>>();
    k_norm     <<<(size_t)BATCH * CCH * NPOS / 4 / 256, 256>>>(out, gamma, beta);
}

// round 3
// speedup vs baseline: 1.2445x; 1.2445x over previous
#include <cuda_runtime.h>
#include <cuda_bf16.h>
#include <math.h>
#include <stdint.h>

// Problem constants
#define BATCH 16
#define CCH   256          // channels
#define NPOS  4096         // 64*64 spatial
#define HEADS 4
#define DHEAD 32
#define INNER 128          // HEADS*DHEAD
#define OC3   384          // 3*INNER
#define SCALEQ 0.17677669529663687f   // 32^-0.5
#define EPSV  1e-5f
#define NSPLIT 8

// ---------------- scratch (static device globals: alloc-free rule) ----------
__device__ float g_qkv[(size_t)BATCH * OC3 * NPOS];          // ~100 MB
__device__ float g_y[(size_t)BATCH * CCH * NPOS];            // ~67 MB
__device__ float g_kmax[BATCH * INNER];
__device__ float g_kinv[BATCH * INNER];
__device__ float g_ctxp[(size_t)BATCH * HEADS * NSPLIT * DHEAD * DHEAD];
__device__ float g_ctx[(size_t)BATCH * HEADS * DHEAD * DHEAD];
__device__ float g_part[BATCH * 128 * 2];                    // per-tile sum / sumsq
__device__ float g_mean[BATCH];
__device__ float g_rstd[BATCH];
// bf16 hi/mid splits: x transposed to [b][p][c]; w kept [o][c]
__device__ __align__(256) __nv_bfloat16 g_xh[(size_t)BATCH * NPOS * CCH];
__device__ __align__(256) __nv_bfloat16 g_xm[(size_t)BATCH * NPOS * CCH];
__device__ __align__(256) __nv_bfloat16 g_wh[OC3 * CCH];
__device__ __align__(256) __nv_bfloat16 g_wm[OC3 * CCH];

// ---------------------------------------------------------------------------
// mma.sync m16n8k16 bf16 (row.col), fp32 accum  — portable sm_80+ ISA
// ---------------------------------------------------------------------------
__device__ __forceinline__ void mma16816(float* c, const uint32_t* a,
                                         const uint32_t* b) {
    asm volatile(
        "mma.sync.aligned.m16n8k16.row.col.f32.bf16.bf16.f32 "
        "{%0,%1,%2,%3}, {%4,%5,%6,%7}, {%8,%9}, {%0,%1,%2,%3};"
        : "+f"(c[0]), "+f"(c[1]), "+f"(c[2]), "+f"(c[3])
        : "r"(a[0]), "r"(a[1]), "r"(a[2]), "r"(a[3]), "r"(b[0]), "r"(b[1]));
}

// ---------------------------------------------------------------------------
// conv kernels: fp32 -> (hi, mid) bf16 split
// ---------------------------------------------------------------------------
__global__ __launch_bounds__(256) void k_convw(const float* __restrict__ w) {
    const int idx = blockIdx.x * 256 + threadIdx.x;     // OC3*CCH = 98304
    float v = w[idx];
    __nv_bfloat16 h = __float2bfloat16(v);
    g_wh[idx] = h;
    g_wm[idx] = __float2bfloat16(v - __bfloat162float(h));
}

// x[b][c][p] fp32  ->  g_xh/g_xm[b][p][c] bf16 (transposed)
__global__ __launch_bounds__(256) void k_convx(const float* __restrict__ x) {
    __shared__ float tile[32][33];
    const int pt = blockIdx.x, ct = blockIdx.y, b = blockIdx.z;
    const int tx = threadIdx.x, ty = threadIdx.y;       // 32 x 8
    const float* xb = x + ((size_t)b * CCH + ct * 32) * NPOS + pt * 32;
#pragma unroll
    for (int j = 0; j < 4; j++)
        tile[ty + j * 8][tx] = xb[(size_t)(ty + j * 8) * NPOS + tx];
    __syncthreads();
    __nv_bfloat16* oh = g_xh + ((size_t)b * NPOS + pt * 32) * CCH + ct * 32;
    __nv_bfloat16* om = g_xm + ((size_t)b * NPOS + pt * 32) * CCH + ct * 32;
#pragma unroll
    for (int j = 0; j < 4; j++) {
        const int pl = ty + j * 8;
        float v = tile[tx][pl];
        __nv_bfloat16 h = __float2bfloat16(v);
        oh[(size_t)pl * CCH + tx] = h;
        om[(size_t)pl * CCH + tx] = __float2bfloat16(v - __bfloat162float(h));
    }
}

// ---------------------------------------------------------------------------
// K1 (mma.sync): qkv[b][o][p] = sum_c w[o][c] * x[b][c][p]
//   D[m=o(128)][n=p(128)],  A = w (row-major o x c),  B = x^T (k-contig p x c)
//   3-term bf16 split: wh*xh + wh*xm + wm*xh
//   smem chunk K=64, padded rows of 72 bf16 (144 B) -> conflict-free frags
// ---------------------------------------------------------------------------
#define ASTR 72
__global__ __launch_bounds__(256) void k_qkv_mma() {
    extern __shared__ __nv_bfloat16 sm[];
    __nv_bfloat16* Awh = sm;                  // 128 x 72
    __nv_bfloat16* Awm = sm + 128 * ASTR;
    __nv_bfloat16* Bxh = sm + 2 * 128 * ASTR;
    __nv_bfloat16* Bxm = sm + 3 * 128 * ASTR;
    const int o0 = blockIdx.x * 128, p0 = blockIdx.y * 128, b = blockIdx.z;
    const int t = threadIdx.x, w = t >> 5, l = t & 31;
    const int wm_ = w & 1, wn_ = w >> 1;          // warp tile: 64(o) x 32(p)
    const int g = l >> 2, tg = l & 3;

    float acc[4][4][4];
#pragma unroll
    for (int i = 0; i < 4; i++)
#pragma unroll
        for (int j = 0; j < 4; j++)
#pragma unroll
            for (int r = 0; r < 4; r++) acc[i][j][r] = 0.f;

    const __nv_bfloat16* gwh = g_wh + (size_t)o0 * CCH;
    const __nv_bfloat16* gwm = g_wm + (size_t)o0 * CCH;
    const __nv_bfloat16* gxh = g_xh + ((size_t)b * NPOS + p0) * CCH;
    const __nv_bfloat16* gxm = g_xm + ((size_t)b * NPOS + p0) * CCH;

    const int lrow = t >> 1;                 // 0..127
    const int loff = (t & 1) * 32;           // 0 or 32 bf16

    for (int kc = 0; kc < 4; kc++) {
        const int k0 = kc * 64;
        // copy 32 bf16 (64 B) per thread per array
#pragma unroll
        for (int q = 0; q < 4; q++) {
            *(uint4*)&Awh[lrow * ASTR + loff + q * 8] =
                *(const uint4*)&gwh[(size_t)lrow * CCH + k0 + loff + q * 8];
            *(uint4*)&Awm[lrow * ASTR + loff + q * 8] =
                *(const uint4*)&gwm[(size_t)lrow * CCH + k0 + loff + q * 8];
            *(uint4*)&Bxh[lrow * ASTR + loff + q * 8] =
                *(const uint4*)&gxh[(size_t)lrow * CCH + k0 + loff + q * 8];
            *(uint4*)&Bxm[lrow * ASTR + loff + q * 8] =
                *(const uint4*)&gxm[(size_t)lrow * CCH + k0 + loff + q * 8];
        }
        __syncthreads();

#pragma unroll
        for (int ks = 0; ks < 4; ks++) {
            const int kb = ks * 16;
            uint32_t ah[4][4], am[4][4], bh[4][2], bm[4][2];
#pragma unroll
            for (int mi = 0; mi < 4; mi++) {
                const int rb = wm_ * 64 + mi * 16;
                ah[mi][0] = *(uint32_t*)&Awh[(rb + g) * ASTR + kb + tg * 2];
                ah[mi][1] = *(uint32_t*)&Awh[(rb + g + 8) * ASTR + kb + tg * 2];
                ah[mi][2] = *(uint32_t*)&Awh[(rb + g) * ASTR + kb + 8 + tg * 2];
                ah[mi][3] = *(uint32_t*)&Awh[(rb + g + 8) * ASTR + kb + 8 + tg * 2];
                am[mi][0] = *(uint32_t*)&Awm[(rb + g) * ASTR + kb + tg * 2];
                am[mi][1] = *(uint32_t*)&Awm[(rb + g + 8) * ASTR + kb + tg * 2];
                am[mi][2] = *(uint32_t*)&Awm[(rb + g) * ASTR + kb + 8 + tg * 2];
                am[mi][3] = *(uint32_t*)&Awm[(rb + g + 8) * ASTR + kb + 8 + tg * 2];
            }
#pragma unroll
            for (int ni = 0; ni < 4; ni++) {
                const int rn = wn_ * 32 + ni * 8 + g;
                bh[ni][0] = *(uint32_t*)&Bxh[rn * ASTR + kb + tg * 2];
                bh[ni][1] = *(uint32_t*)&Bxh[rn * ASTR + kb + 8 + tg * 2];
                bm[ni][0] = *(uint32_t*)&Bxm[rn * ASTR + kb + tg * 2];
                bm[ni][1] = *(uint32_t*)&Bxm[rn * ASTR + kb + 8 + tg * 2];
            }
#pragma unroll
            for (int mi = 0; mi < 4; mi++)
#pragma unroll
                for (int ni = 0; ni < 4; ni++) {
                    mma16816(acc[mi][ni], ah[mi], bh[ni]);
                    mma16816(acc[mi][ni], ah[mi], bm[ni]);
                    mma16816(acc[mi][ni], am[mi], bh[ni]);
                }
        }
        __syncthreads();
    }

    // epilogue: D[o][p] -> g_qkv
    float* outb = g_qkv + (size_t)b * OC3 * NPOS;
#pragma unroll
    for (int mi = 0; mi < 4; mi++) {
        const int o = o0 + wm_ * 64 + mi * 16 + g;
#pragma unroll
        for (int ni = 0; ni < 4; ni++) {
            const int p = p0 + wn_ * 32 + ni * 8 + tg * 2;
            *(float2*)&outb[(size_t)o * NPOS + p] =
                make_float2(acc[mi][ni][0], acc[mi][ni][1]);
            *(float2*)&outb[(size_t)(o + 8) * NPOS + p] =
                make_float2(acc[mi][ni][2], acc[mi][ni][3]);
        }
    }
}
#define SMEM_K1 (4 * 128 * ASTR * 2)

// ---------------------------------------------------------------------------
// K2: per (b, k-channel) row: max and 1/sum(exp) over n (single global pass)
// ---------------------------------------------------------------------------
__global__ __launch_bounds__(256) void k_kstats() {
    const int row = blockIdx.x;              // 0 .. B*INNER-1
    const int b = row >> 7, kc = row & 127;
    const float* kr = g_qkv + ((size_t)b * OC3 + INNER + kc) * NPOS;
    const int t = threadIdx.x;
    float v[16];
    float m = -1e30f;
#pragma unroll
    for (int i = 0; i < 16; i++) { v[i] = kr[i * 256 + t]; m = fmaxf(m, v[i]); }
    __shared__ float red[8];
#pragma unroll
    for (int o = 16; o > 0; o >>= 1) m = fmaxf(m, __shfl_xor_sync(0xffffffffu, m, o));
    if ((t & 31) == 0) red[t >> 5] = m;
    __syncthreads();
    if (t < 32) {
        float mm = (t < 8) ? red[t] : -1e30f;
#pragma unroll
        for (int o = 16; o > 0; o >>= 1) mm = fmaxf(mm, __shfl_xor_sync(0xffffffffu, mm, o));
        if (t == 0) red[0] = mm;
    }
    __syncthreads();
    m = red[0];
    __syncthreads();
    float s = 0.f;
#pragma unroll
    for (int i = 0; i < 16; i++) s += __expf(v[i] - m);
#pragma unroll
    for (int o = 16; o > 0; o >>= 1) s += __shfl_xor_sync(0xffffffffu, s, o);
    if ((t & 31) == 0) red[t >> 5] = s;
    __syncthreads();
    if (t == 0) {
        float ss = 0.f;
        for (int i = 0; i < 8; i++) ss += red[i];
        g_kmax[row] = m;
        g_kinv[row] = 1.0f / ss;
    }
}

// ---------------------------------------------------------------------------
// K3: split-K context partials: ctxp[b,h,s,d,e] = sum_{n in slice} softk[d,n]*v[e,n]
// ---------------------------------------------------------------------------
__global__ __launch_bounds__(256) void k_context() {
    const int s = blockIdx.x, h = blockIdx.y, b = blockIdx.z;
    __shared__ float ks[32 * 129];
    __shared__ float vs[32 * 129];
    __shared__ float smax[32], sinv[32];
    const int t = threadIdx.x;
    const int e = t & 31, dg = t >> 5;   // dg 0..7 -> d = dg*4 + i
    float acc[4] = {0.f, 0.f, 0.f, 0.f};
    const float* kbase = g_qkv + ((size_t)b * OC3 + INNER + h * DHEAD) * NPOS;
    const float* vbase = g_qkv + ((size_t)b * OC3 + 2 * INNER + h * DHEAD) * NPOS;
    if (t < 32) {
        smax[t] = g_kmax[b * INNER + h * DHEAD + t];
        sinv[t] = g_kinv[b * INNER + h * DHEAD + t];
    }
    __syncthreads();
    for (int tile = 0; tile < 4; tile++) {
        const int n0 = s * 512 + tile * 128;
#pragma unroll
        for (int i = 0; i < 16; i++) {
            int idx = i * 256 + t;
            int d = idx >> 7, nn = idx & 127;
            float kraw = kbase[(size_t)d * NPOS + n0 + nn];
            ks[d * 129 + nn] = __expf(kraw - smax[d]) * sinv[d];
            vs[d * 129 + nn] = vbase[(size_t)d * NPOS + n0 + nn];
        }
        __syncthreads();
        for (int nn = 0; nn < 128; nn++) {
            float vv = vs[e * 129 + nn];
#pragma unroll
            for (int i = 0; i < 4; i++) acc[i] += ks[(dg * 4 + i) * 129 + nn] * vv;
        }
        __syncthreads();
    }
    float* cp = g_ctxp + ((size_t)(b * HEADS + h) * NSPLIT + s) * 1024;
#pragma unroll
    for (int i = 0; i < 4; i++) cp[(dg * 4 + i) * 32 + e] = acc[i];
}

__global__ void k_ctx_reduce() {
    const int idx = blockIdx.x * 256 + threadIdx.x;   // 65536 total
    const int bh = idx >> 10, de = idx & 1023;
    float s = 0.f;
#pragma unroll
    for (int j = 0; j < NSPLIT; j++)
        s += g_ctxp[((size_t)bh * NSPLIT + j) * 1024 + de];
    g_ctx[(size_t)bh * 1024 + de] = s;
}

// ---------------------------------------------------------------------------
// K4: fused  q-softmax(d) -> inner = ctx^T * softq -> y = w_out*inner + b_out
//     plus deterministic per-tile sum/sumsq partials for GroupNorm.
// ---------------------------------------------------------------------------
__global__ __launch_bounds__(256) void k_attn_out(const float* __restrict__ wout,
                                                  const float* __restrict__ bout) {
    __shared__ float sq[128 * 32];       // q channels [c][p]
    __shared__ float inner_s[128 * 32];  // [e][p]
    __shared__ float cbuf[4096];         // ctx, then w_out chunks
    const int tile = blockIdx.x, b = blockIdx.y;
    const int col0 = tile * 32;
    const int t = threadIdx.x;
    const float* qbase = g_qkv + (size_t)b * OC3 * NPOS;

    // load q tile + ctx
#pragma unroll
    for (int i = 0; i < 16; i++) {
        int idx = i * 256 + t;
        int c = idx >> 5, p = idx & 31;
        sq[c * 32 + p] = qbase[(size_t)c * NPOS + col0 + p];
    }
#pragma unroll
    for (int i = 0; i < 16; i++)
        cbuf[i * 256 + t] = g_ctx[(size_t)b * 4096 + i * 256 + t];
    __syncthreads();

    // softmax over d per (h, p) column, * SCALE
    if (t < 128) {
        const int h = t >> 5, p = t & 31;
        float m = -1e30f;
#pragma unroll
        for (int d = 0; d < 32; d++) m = fmaxf(m, sq[(h * 32 + d) * 32 + p]);
        float ssum = 0.f;
#pragma unroll
        for (int d = 0; d < 32; d++) ssum += __expf(sq[(h * 32 + d) * 32 + p] - m);
        const float inv = SCALEQ / ssum;
#pragma unroll
        for (int d = 0; d < 32; d++)
            sq[(h * 32 + d) * 32 + p] = __expf(sq[(h * 32 + d) * 32 + p] - m) * inv;
    }
    __syncthreads();

    // stage 2: inner[e][p] = sum_d ctx[h][d][e] * softq[h*32+d][p]
    {
        const int p = t & 31, eg = t >> 5;       // eg 0..7
        const int h = eg >> 1;
        const int e0 = (eg & 1) * 16;
        float sqv[32];
#pragma unroll
        for (int d = 0; d < 32; d++) sqv[d] = sq[(h * 32 + d) * 32 + p];
        float acc2[16];
#pragma unroll
        for (int i = 0; i < 16; i++) acc2[i] = 0.f;
#pragma unroll
        for (int d = 0; d < 32; d++) {
            const float qd = sqv[d];
#pragma unroll
            for (int i4 = 0; i4 < 4; i4++) {
                float4 c4 = *(float4*)&cbuf[h * 1024 + d * 32 + e0 + i4 * 4];
                acc2[i4 * 4 + 0] += c4.x * qd;
                acc2[i4 * 4 + 1] += c4.y * qd;
                acc2[i4 * 4 + 2] += c4.z * qd;
                acc2[i4 * 4 + 3] += c4.w * qd;
            }
        }
#pragma unroll
        for (int i = 0; i < 16; i++)
            inner_s[(h * 32 + e0 + i) * 32 + p] = acc2[i];
    }
    __syncthreads();

    // stage 3: y[o][p] = sum_e w_out[o][e]*inner[e][p]; w chunks staged in cbuf
    const int ty = t >> 3, tx = t & 7;           // o = ty*8.., p = tx*4..
    float acc3[8][4];
#pragma unroll
    for (int i = 0; i < 8; i++)
#pragma unroll
        for (int j = 0; j < 4; j++) acc3[i][j] = 0.f;

    for (int et = 0; et < 8; et++) {
        {   // load w chunk transposed: cbuf[e'][o], 16 x 256
            const int o = t;
#pragma unroll
            for (int q = 0; q < 4; q++) {
                float4 wv = *(const float4*)&wout[(size_t)o * INNER + et * 16 + q * 4];
                cbuf[(q * 4 + 0) * 256 + o] = wv.x;
                cbuf[(q * 4 + 1) * 256 + o] = wv.y;
                cbuf[(q * 4 + 2) * 256 + o] = wv.z;
                cbuf[(q * 4 + 3) * 256 + o] = wv.w;
            }
        }
        __syncthreads();
#pragma unroll
        for (int ee = 0; ee < 16; ee++) {
            float4 a0 = *(float4*)&cbuf[ee * 256 + ty * 8];
            float4 a1 = *(float4*)&cbuf[ee * 256 + ty * 8 + 4];
            float4 bv = *(float4*)&inner_s[(et * 16 + ee) * 32 + tx * 4];
            float av[8] = {a0.x, a0.y, a0.z, a0.w, a1.x, a1.y, a1.z, a1.w};
            float bb[4] = {bv.x, bv.y, bv.z, bv.w};
#pragma unroll
            for (int i = 0; i < 8; i++)
#pragma unroll
                for (int j = 0; j < 4; j++) acc3[i][j] += av[i] * bb[j];
        }
        __syncthreads();
    }

    // bias + write + partial sums (reuse sq space for reduction scratch)
    float lsum = 0.f, lsq = 0.f;
    float* yb = g_y + (size_t)b * CCH * NPOS;
#pragma unroll
    for (int i = 0; i < 8; i++) {
        const int o = ty * 8 + i;
        const float bo = bout[o];
        float4 v = make_float4(acc3[i][0] + bo, acc3[i][1] + bo,
                               acc3[i][2] + bo, acc3[i][3] + bo);
        *(float4*)&yb[(size_t)o * NPOS + col0 + tx * 4] = v;
        lsum += v.x + v.y + v.z + v.w;
        lsq  += v.x * v.x + v.y * v.y + v.z * v.z + v.w * v.w;
    }
    float* rs = sq;        // sq is dead now
    float* rq = sq + 8;
#pragma unroll
    for (int o = 16; o > 0; o >>= 1) {
        lsum += __shfl_xor_sync(0xffffffffu, lsum, o);
        lsq  += __shfl_xor_sync(0xffffffffu, lsq, o);
    }
    if ((t & 31) == 0) { rs[t >> 5] = lsum; rq[t >> 5] = lsq; }
    __syncthreads();
    if (t == 0) {
        float a = 0.f, q = 0.f;
        for (int i = 0; i < 8; i++) { a += rs[i]; q += rq[i]; }
        g_part[(b * 128 + tile) * 2 + 0] = a;
        g_part[(b * 128 + tile) * 2 + 1] = q;
    }
}

// ---------------------------------------------------------------------------
// K5: combine partials per batch (double precision)
// ---------------------------------------------------------------------------
__global__ void k_gn_stats() {
    const int b = blockIdx.x;
    const int t = threadIdx.x;    // 128
    double s = (double)g_part[(b * 128 + t) * 2 + 0];
    double q = (double)g_part[(b * 128 + t) * 2 + 1];
#pragma unroll
    for (int o = 16; o > 0; o >>= 1) {
        s += __shfl_xor_sync(0xffffffffu, s, o);
        q += __shfl_xor_sync(0xffffffffu, q, o);
    }
    __shared__ double ss[4], qq[4];
    if ((t & 31) == 0) { ss[t >> 5] = s; qq[t >> 5] = q; }
    __syncthreads();
    if (t == 0) {
        double S = 0.0, Q = 0.0;
        for (int i = 0; i < 4; i++) { S += ss[i]; Q += qq[i]; }
        const double cnt = (double)CCH * (double)NPOS;
        const double mean = S / cnt;
        const double var = Q / cnt - mean * mean;
        g_mean[b] = (float)mean;
        g_rstd[b] = (float)(1.0 / sqrt(var + (double)EPSV));
    }
}

// ---------------------------------------------------------------------------
// K6: normalize + gamma/beta
// ---------------------------------------------------------------------------
__global__ __launch_bounds__(256) void k_norm(float* __restrict__ out,
                                              const float* __restrict__ gamma,
                                              const float* __restrict__ beta) {
    const size_t idx4 = (size_t)blockIdx.x * 256 + threadIdx.x;
    const size_t base = idx4 * 4;
    const int b = (int)(base / ((size_t)CCH * NPOS));
    const int c = (int)(base / NPOS) & 255;
    const float mean = g_mean[b], rstd = g_rstd[b];
    const float g = gamma[c] * rstd, bt = beta[c];
    float4 v = *(float4*)&g_y[base];
    v.x = (v.x - mean) * g + bt;
    v.y = (v.y - mean) * g + bt;
    v.z = (v.z - mean) * g + bt;
    v.w = (v.w - mean) * g + bt;
    *(float4*)&out[base] = v;
}

// ---------------------------------------------------------------------------
extern "C" void kernel_launch(void* const* d_in, const int* in_sizes, int n_in,
                              void* d_out, int out_size) {
    const float* x     = (const float*)d_in[0];
    const float* wqkv  = (const float*)d_in[1];
    const float* wout  = (const float*)d_in[2];
    const float* bout  = (const float*)d_in[3];
    const float* gamma = (const float*)d_in[4];
    const float* beta  = (const float*)d_in[5];
    float* out = (float*)d_out;

    cudaFuncSetAttribute(k_qkv_mma, cudaFuncAttributeMaxDynamicSharedMemorySize,
                         SMEM_K1);

    k_convw    <<<OC3, 256>>>(wqkv);
    k_convx    <<<dim3(NPOS / 32, CCH / 32, BATCH), dim3(32, 8)>>>(x);
    k_qkv_mma  <<<dim3(OC3 / 128, NPOS / 128, BATCH), 256, SMEM_K1>>>();
    k_kstats   <<<BATCH * INNER, 256>>>();
    k_context  <<<dim3(NSPLIT, HEADS, BATCH), 256>>>();
    k_ctx_reduce<<<(BATCH * HEADS * DHEAD * DHEAD) / 256, 256>>>();
    k_attn_out <<<dim3(NPOS / 32, BATCH), 256>>>(wout, bout);
    k_gn_stats <<<BATCH, 128>>>();
    k_norm     <<<(size_t)BATCH * CCH * NPOS / 4 / 256, 256>>>(out, gamma, beta);
}

// round 4
// speedup vs baseline: 1.3787x; 1.1078x over previous
#include <cuda_runtime.h>
#include <cuda_bf16.h>
#include <math.h>
#include <stdint.h>

// Problem constants
#define BATCH 16
#define CCH   256          // channels
#define NPOS  4096         // 64*64 spatial
#define HEADS 4
#define DHEAD 32
#define INNER 128          // HEADS*DHEAD
#define OC3   384          // 3*INNER
#define SCALEQ 0.17677669529663687f   // 32^-0.5
#define EPSV  1e-5f
#define NSPLIT 8

// ---------------- scratch (static device globals: alloc-free rule) ----------
__device__ float g_qkv[(size_t)BATCH * OC3 * NPOS];          // ~100 MB
__device__ float g_y[(size_t)BATCH * CCH * NPOS];            // ~67 MB
__device__ float g_kmax[BATCH * INNER];
__device__ float g_kinv[BATCH * INNER];
__device__ float g_ctxp[(size_t)BATCH * HEADS * NSPLIT * DHEAD * DHEAD];
__device__ float g_ctx[(size_t)BATCH * HEADS * DHEAD * DHEAD];
__device__ float g_part[BATCH * 128 * 2];                    // per-tile sum / sumsq
__device__ float g_mean[BATCH];
__device__ float g_rstd[BATCH];
// bf16 hi/mid splits: x transposed to [b][p][c]; w kept [o][c]
__device__ __align__(256) __nv_bfloat16 g_xh[(size_t)BATCH * NPOS * CCH];
__device__ __align__(256) __nv_bfloat16 g_xm[(size_t)BATCH * NPOS * CCH];
__device__ __align__(256) __nv_bfloat16 g_wh[OC3 * CCH];
__device__ __align__(256) __nv_bfloat16 g_wm[OC3 * CCH];
__device__ __align__(256) __nv_bfloat16 g_w2h[CCH * INNER];  // w_out split
__device__ __align__(256) __nv_bfloat16 g_w2m[CCH * INNER];

// ---------------------------------------------------------------------------
// mma / ldmatrix / cp.async helpers (portable sm_80+ ISA)
// ---------------------------------------------------------------------------
__device__ __forceinline__ void mma16816(float* c, const uint32_t* a,
                                         const uint32_t* b) {
    asm volatile(
        "mma.sync.aligned.m16n8k16.row.col.f32.bf16.bf16.f32 "
        "{%0,%1,%2,%3}, {%4,%5,%6,%7}, {%8,%9}, {%0,%1,%2,%3};"
        : "+f"(c[0]), "+f"(c[1]), "+f"(c[2]), "+f"(c[3])
        : "r"(a[0]), "r"(a[1]), "r"(a[2]), "r"(a[3]), "r"(b[0]), "r"(b[1]));
}
__device__ __forceinline__ uint32_t sm_addr(const void* p) {
    uint32_t a;
    asm("{ .reg .u64 t; cvta.to.shared.u64 t, %1; cvt.u32.u64 %0, t; }"
        : "=r"(a) : "l"(p));
    return a;
}
__device__ __forceinline__ void ldsm_x4(uint32_t& r0, uint32_t& r1,
                                        uint32_t& r2, uint32_t& r3, uint32_t a) {
    asm volatile("ldmatrix.sync.aligned.m8n8.x4.shared.b16 {%0,%1,%2,%3}, [%4];"
                 : "=r"(r0), "=r"(r1), "=r"(r2), "=r"(r3) : "r"(a));
}
__device__ __forceinline__ void cp16(uint32_t s, const void* g) {
    asm volatile("cp.async.cg.shared.global [%0], [%1], 16;" :: "r"(s), "l"(g));
}
__device__ __forceinline__ void cp_commit_wait() {
    asm volatile("cp.async.commit_group;");
    asm volatile("cp.async.wait_group 0;");
}

// ---------------------------------------------------------------------------
// conv kernels: fp32 -> (hi, mid) bf16 split
// ---------------------------------------------------------------------------
__global__ __launch_bounds__(256) void k_convw(const float* __restrict__ w) {
    const int idx = blockIdx.x * 256 + threadIdx.x;     // OC3*CCH = 98304
    float v = w[idx];
    __nv_bfloat16 h = __float2bfloat16(v);
    g_wh[idx] = h;
    g_wm[idx] = __float2bfloat16(v - __bfloat162float(h));
}
__global__ __launch_bounds__(256) void k_convw2(const float* __restrict__ w) {
    const int idx = blockIdx.x * 256 + threadIdx.x;     // CCH*INNER = 32768
    float v = w[idx];
    __nv_bfloat16 h = __float2bfloat16(v);
    g_w2h[idx] = h;
    g_w2m[idx] = __float2bfloat16(v - __bfloat162float(h));
}

// x[b][c][p] fp32  ->  g_xh/g_xm[b][p][c] bf16 (transposed)
__global__ __launch_bounds__(256) void k_convx(const float* __restrict__ x) {
    __shared__ float tile[32][33];
    const int pt = blockIdx.x, ct = blockIdx.y, b = blockIdx.z;
    const int tx = threadIdx.x, ty = threadIdx.y;       // 32 x 8
    const float* xb = x + ((size_t)b * CCH + ct * 32) * NPOS + pt * 32;
#pragma unroll
    for (int j = 0; j < 4; j++)
        tile[ty + j * 8][tx] = xb[(size_t)(ty + j * 8) * NPOS + tx];
    __syncthreads();
    __nv_bfloat16* oh = g_xh + ((size_t)b * NPOS + pt * 32) * CCH + ct * 32;
    __nv_bfloat16* om = g_xm + ((size_t)b * NPOS + pt * 32) * CCH + ct * 32;
#pragma unroll
    for (int j = 0; j < 4; j++) {
        const int pl = ty + j * 8;
        float v = tile[tx][pl];
        __nv_bfloat16 h = __float2bfloat16(v);
        oh[(size_t)pl * CCH + tx] = h;
        om[(size_t)pl * CCH + tx] = __float2bfloat16(v - __bfloat162float(h));
    }
}

// ---------------------------------------------------------------------------
// K1 (mma.sync + ldmatrix + cp.async): qkv[b][o][p] = sum_c w[o][c]*x[b][c][p]
//   D[m=o(128)][n=p(128)], warp tile 64x32. 3-term bf16 split.
//   smem rows 72 bf16 (144 B): conflict-free stores & ldmatrix.
//   __launch_bounds__(256,2): 2 blocks/SM -> cross-block load/MMA overlap.
// ---------------------------------------------------------------------------
#define ASTR 72
__global__ __launch_bounds__(256, 2) void k_qkv_mma() {
    extern __shared__ __nv_bfloat16 sm[];
    __nv_bfloat16* Awh = sm;                  // 128 x 72
    __nv_bfloat16* Awm = sm + 128 * ASTR;
    __nv_bfloat16* Bxh = sm + 2 * 128 * ASTR;
    __nv_bfloat16* Bxm = sm + 3 * 128 * ASTR;
    const int o0 = blockIdx.x * 128, p0 = blockIdx.y * 128, b = blockIdx.z;
    const int t = threadIdx.x, w = t >> 5, l = t & 31;
    const int wm_ = w & 1, wn_ = w >> 1;          // warp tile: 64(o) x 32(p)

    float acc[4][4][4];
#pragma unroll
    for (int i = 0; i < 4; i++)
#pragma unroll
        for (int j = 0; j < 4; j++)
#pragma unroll
            for (int r = 0; r < 4; r++) acc[i][j][r] = 0.f;

    const __nv_bfloat16* gwh = g_wh + (size_t)o0 * CCH;
    const __nv_bfloat16* gwm = g_wm + (size_t)o0 * CCH;
    const __nv_bfloat16* gxh = g_xh + ((size_t)b * NPOS + p0) * CCH;
    const __nv_bfloat16* gxm = g_xm + ((size_t)b * NPOS + p0) * CCH;

    const int lrow = t >> 1;                 // 0..127
    const int loff = (t & 1) * 32;           // 0 or 32 bf16
    const uint32_t sAwh = sm_addr(Awh), sAwm = sm_addr(Awm);
    const uint32_t sBxh = sm_addr(Bxh), sBxm = sm_addr(Bxm);
    const uint32_t cp_dst = (uint32_t)(lrow * ASTR + loff) * 2;
    const size_t   cp_src = (size_t)lrow * CCH + loff;

    // ldmatrix lane offset: row = (l&15), colhalf = (l>>4)*8
    const uint32_t lmoff = (uint32_t)((l & 15) * ASTR + (l >> 4) * 8) * 2;

    for (int kc = 0; kc < 4; kc++) {
        const int k0 = kc * 64;
#pragma unroll
        for (int q = 0; q < 4; q++) {
            cp16(sAwh + cp_dst + q * 16, gwh + cp_src + k0 + q * 8);
            cp16(sAwm + cp_dst + q * 16, gwm + cp_src + k0 + q * 8);
            cp16(sBxh + cp_dst + q * 16, gxh + cp_src + k0 + q * 8);
            cp16(sBxm + cp_dst + q * 16, gxm + cp_src + k0 + q * 8);
        }
        cp_commit_wait();
        __syncthreads();

#pragma unroll
        for (int ks = 0; ks < 4; ks++) {
            const uint32_t kboff = (uint32_t)(ks * 16) * 2;
            uint32_t bh[4][2], bm[4][2];
            // B frags: rows wn_*32 (+16) cover ni pairs {0,1},{2,3}
            {
                uint32_t base = sBxh + lmoff + kboff + (uint32_t)(wn_ * 32) * ASTR * 2;
                ldsm_x4(bh[0][0], bh[1][0], bh[0][1], bh[1][1], base);
                ldsm_x4(bh[2][0], bh[3][0], bh[2][1], bh[3][1],
                        base + (uint32_t)(16 * ASTR * 2));
                base = sBxm + lmoff + kboff + (uint32_t)(wn_ * 32) * ASTR * 2;
                ldsm_x4(bm[0][0], bm[1][0], bm[0][1], bm[1][1], base);
                ldsm_x4(bm[2][0], bm[3][0], bm[2][1], bm[3][1],
                        base + (uint32_t)(16 * ASTR * 2));
            }
#pragma unroll
            for (int mi = 0; mi < 4; mi++) {
                const uint32_t roff =
                    (uint32_t)((wm_ * 64 + mi * 16) * ASTR) * 2 + lmoff + kboff;
                uint32_t ah[4], am[4];
                ldsm_x4(ah[0], ah[1], ah[2], ah[3], sAwh + roff);
                ldsm_x4(am[0], am[1], am[2], am[3], sAwm + roff);
#pragma unroll
                for (int ni = 0; ni < 4; ni++) {
                    mma16816(acc[mi][ni], ah, bh[ni]);
                    mma16816(acc[mi][ni], ah, bm[ni]);
                    mma16816(acc[mi][ni], am, bh[ni]);
                }
            }
        }
        __syncthreads();
    }

    // epilogue: D[o][p] -> g_qkv
    const int g = l >> 2, tg = l & 3;
    float* outb = g_qkv + (size_t)b * OC3 * NPOS;
#pragma unroll
    for (int mi = 0; mi < 4; mi++) {
        const int o = o0 + wm_ * 64 + mi * 16 + g;
#pragma unroll
        for (int ni = 0; ni < 4; ni++) {
            const int p = p0 + wn_ * 32 + ni * 8 + tg * 2;
            *(float2*)&outb[(size_t)o * NPOS + p] =
                make_float2(acc[mi][ni][0], acc[mi][ni][1]);
            *(float2*)&outb[(size_t)(o + 8) * NPOS + p] =
                make_float2(acc[mi][ni][2], acc[mi][ni][3]);
        }
    }
}
#define SMEM_K1 (4 * 128 * ASTR * 2)

// ---------------------------------------------------------------------------
// K2: per (b, k-channel) row: max and 1/sum(exp) over n (single global pass)
// ---------------------------------------------------------------------------
__global__ __launch_bounds__(256) void k_kstats() {
    const int row = blockIdx.x;              // 0 .. B*INNER-1
    const int b = row >> 7, kc = row & 127;
    const float* kr = g_qkv + ((size_t)b * OC3 + INNER + kc) * NPOS;
    const int t = threadIdx.x;
    float v[16];
    float m = -1e30f;
#pragma unroll
    for (int i = 0; i < 16; i++) { v[i] = kr[i * 256 + t]; m = fmaxf(m, v[i]); }
    __shared__ float red[8];
#pragma unroll
    for (int o = 16; o > 0; o >>= 1) m = fmaxf(m, __shfl_xor_sync(0xffffffffu, m, o));
    if ((t & 31) == 0) red[t >> 5] = m;
    __syncthreads();
    if (t < 32) {
        float mm = (t < 8) ? red[t] : -1e30f;
#pragma unroll
        for (int o = 16; o > 0; o >>= 1) mm = fmaxf(mm, __shfl_xor_sync(0xffffffffu, mm, o));
        if (t == 0) red[0] = mm;
    }
    __syncthreads();
    m = red[0];
    __syncthreads();
    float s = 0.f;
#pragma unroll
    for (int i = 0; i < 16; i++) s += __expf(v[i] - m);
#pragma unroll
    for (int o = 16; o > 0; o >>= 1) s += __shfl_xor_sync(0xffffffffu, s, o);
    if ((t & 31) == 0) red[t >> 5] = s;
    __syncthreads();
    if (t == 0) {
        float ss = 0.f;
        for (int i = 0; i < 8; i++) ss += red[i];
        g_kmax[row] = m;
        g_kinv[row] = 1.0f / ss;
    }
}

// ---------------------------------------------------------------------------
// K3: split-K context partials
// ---------------------------------------------------------------------------
__global__ __launch_bounds__(256) void k_context() {
    const int s = blockIdx.x, h = blockIdx.y, b = blockIdx.z;
    __shared__ float ks[32 * 129];
    __shared__ float vs[32 * 129];
    __shared__ float smax[32], sinv[32];
    const int t = threadIdx.x;
    const int e = t & 31, dg = t >> 5;
    float acc[4] = {0.f, 0.f, 0.f, 0.f};
    const float* kbase = g_qkv + ((size_t)b * OC3 + INNER + h * DHEAD) * NPOS;
    const float* vbase = g_qkv + ((size_t)b * OC3 + 2 * INNER + h * DHEAD) * NPOS;
    if (t < 32) {
        smax[t] = g_kmax[b * INNER + h * DHEAD + t];
        sinv[t] = g_kinv[b * INNER + h * DHEAD + t];
    }
    __syncthreads();
    for (int tile = 0; tile < 4; tile++) {
        const int n0 = s * 512 + tile * 128;
#pragma unroll
        for (int i = 0; i < 16; i++) {
            int idx = i * 256 + t;
            int d = idx >> 7, nn = idx & 127;
            float kraw = kbase[(size_t)d * NPOS + n0 + nn];
            ks[d * 129 + nn] = __expf(kraw - smax[d]) * sinv[d];
            vs[d * 129 + nn] = vbase[(size_t)d * NPOS + n0 + nn];
        }
        __syncthreads();
        for (int nn = 0; nn < 128; nn++) {
            float vv = vs[e * 129 + nn];
#pragma unroll
            for (int i = 0; i < 4; i++) acc[i] += ks[(dg * 4 + i) * 129 + nn] * vv;
        }
        __syncthreads();
    }
    float* cp = g_ctxp + ((size_t)(b * HEADS + h) * NSPLIT + s) * 1024;
#pragma unroll
    for (int i = 0; i < 4; i++) cp[(dg * 4 + i) * 32 + e] = acc[i];
}

__global__ void k_ctx_reduce() {
    const int idx = blockIdx.x * 256 + threadIdx.x;   // 65536 total
    const int bh = idx >> 10, de = idx & 1023;
    float s = 0.f;
#pragma unroll
    for (int j = 0; j < NSPLIT; j++)
        s += g_ctxp[((size_t)bh * NSPLIT + j) * 1024 + de];
    g_ctx[(size_t)bh * 1024 + de] = s;
}

// ---------------------------------------------------------------------------
// K4: q-softmax -> inner = ctx^T*softq (FFMA, small) -> y = w_out*inner + b
//     out-projection now tensor-core (3-term bf16 split, ldmatrix).
// Dynamic smem layout (58368 B):
//   [0,16384)       sq fp32 [128c][32p]
//   [16384,40960)   union: ctx fp32[4096] | A chunks hi(12288)+mid(12288)
//   [40960,49664)   inner hi bf16 [32p][136e-pad]
//   [49664,58368)   inner mid
// ---------------------------------------------------------------------------
#define K4_SMEM 58368
#define ISTR 136
__global__ __launch_bounds__(256) void k_attn_out(const float* __restrict__ bout) {
    extern __shared__ char sm4[];
    float* sq  = (float*)sm4;
    float* ctx = (float*)(sm4 + 16384);
    __nv_bfloat16* Ah = (__nv_bfloat16*)(sm4 + 16384);
    __nv_bfloat16* Am = (__nv_bfloat16*)(sm4 + 16384 + 12288);
    __nv_bfloat16* iH = (__nv_bfloat16*)(sm4 + 40960);
    __nv_bfloat16* iM = (__nv_bfloat16*)(sm4 + 49664);
    const int tile = blockIdx.x, b = blockIdx.y;
    const int col0 = tile * 32;
    const int t = threadIdx.x, l = t & 31;
    const float* qbase = g_qkv + (size_t)b * OC3 * NPOS;

    // stage 1: load q tile + ctx
#pragma unroll
    for (int i = 0; i < 16; i++) {
        int idx = i * 256 + t;
        int c = idx >> 5, p = idx & 31;
        sq[c * 32 + p] = qbase[(size_t)c * NPOS + col0 + p];
    }
#pragma unroll
    for (int i = 0; i < 16; i++)
        ctx[i * 256 + t] = g_ctx[(size_t)b * 4096 + i * 256 + t];
    __syncthreads();

    // softmax over d per (head, p) column, * SCALE
    if (t < 128) {
        const int hh = t >> 5, p = t & 31;
        float m = -1e30f;
#pragma unroll
        for (int d = 0; d < 32; d++) m = fmaxf(m, sq[(hh * 32 + d) * 32 + p]);
        float ssum = 0.f;
#pragma unroll
        for (int d = 0; d < 32; d++) ssum += __expf(sq[(hh * 32 + d) * 32 + p] - m);
        const float inv = SCALEQ / ssum;
#pragma unroll
        for (int d = 0; d < 32; d++)
            sq[(hh * 32 + d) * 32 + p] = __expf(sq[(hh * 32 + d) * 32 + p] - m) * inv;
    }
    __syncthreads();

    // stage 2: inner[e][p] = sum_d ctx[hh][d][e]*softq -> write [p][e] bf16 split
    {
        const int p = t & 31, eg = t >> 5;
        const int hh = eg >> 1;
        const int e0 = (eg & 1) * 16;
        float sqv[32];
#pragma unroll
        for (int d = 0; d < 32; d++) sqv[d] = sq[(hh * 32 + d) * 32 + p];
        float acc2[16];
#pragma unroll
        for (int i = 0; i < 16; i++) acc2[i] = 0.f;
#pragma unroll
        for (int d = 0; d < 32; d++) {
            const float qd = sqv[d];
#pragma unroll
            for (int i4 = 0; i4 < 4; i4++) {
                float4 c4 = *(float4*)&ctx[hh * 1024 + d * 32 + e0 + i4 * 4];
                acc2[i4 * 4 + 0] += c4.x * qd;
                acc2[i4 * 4 + 1] += c4.y * qd;
                acc2[i4 * 4 + 2] += c4.z * qd;
                acc2[i4 * 4 + 3] += c4.w * qd;
            }
        }
#pragma unroll
        for (int i = 0; i < 16; i++) {
            float v = acc2[i];
            __nv_bfloat16 h = __float2bfloat16(v);
            iH[p * ISTR + hh * 32 + e0 + i] = h;
            iM[p * ISTR + hh * 32 + e0 + i] =
                __float2bfloat16(v - __bfloat162float(h));
        }
    }
    __syncthreads();   // inner done; ctx area can be reused for A chunks

    // stage 3 (mma): y[o][p] = sum_e w_out[o][e]*inner[e][p]
    const int wid = t >> 5, wo = wid >> 1, wp = wid & 1;  // warp tile 64o x 16p
    const int g = l >> 2, tg = l & 3;
    float acc[4][2][4];
#pragma unroll
    for (int i = 0; i < 4; i++)
#pragma unroll
        for (int j = 0; j < 2; j++)
#pragma unroll
            for (int r = 0; r < 4; r++) acc[i][j][r] = 0.f;

    const uint32_t sAh = sm_addr(Ah), sAm = sm_addr(Am);
    const uint32_t siH = sm_addr(iH), siM = sm_addr(iM);
    const uint32_t lmrow = (uint32_t)(l & 15);
    const uint32_t lmc8b = (uint32_t)((l >> 4) * 8) * 2;

    for (int ec = 0; ec < 8; ec++) {
        // stage w_out chunk [256o][16e] hi+mid; row stride 24 bf16 (48 B)
        {
            const int o = t;
            uint4 v0 = *(const uint4*)&g_w2h[o * INNER + ec * 16];
            uint4 v1 = *(const uint4*)&g_w2h[o * INNER + ec * 16 + 8];
            *(uint4*)&Ah[o * 24 + 0] = v0;
            *(uint4*)&Ah[o * 24 + 8] = v1;
            uint4 m0 = *(const uint4*)&g_w2m[o * INNER + ec * 16];
            uint4 m1 = *(const uint4*)&g_w2m[o * INNER + ec * 16 + 8];
            *(uint4*)&Am[o * 24 + 0] = m0;
            *(uint4*)&Am[o * 24 + 8] = m1;
        }
        __syncthreads();

        uint32_t bh[2][2], bm[2][2];
        {
            uint32_t base = (uint32_t)((wp * 16 + lmrow) * ISTR + ec * 16) * 2 + lmc8b;
            ldsm_x4(bh[0][0], bh[1][0], bh[0][1], bh[1][1], siH + base);
            ldsm_x4(bm[0][0], bm[1][0], bm[0][1], bm[1][1], siM + base);
        }
#pragma unroll
        for (int mi = 0; mi < 4; mi++) {
            const uint32_t ro = (uint32_t)((wo * 64 + mi * 16 + lmrow) * 24) * 2 + lmc8b;
            uint32_t ah[4], am[4];
            ldsm_x4(ah[0], ah[1], ah[2], ah[3], sAh + ro);
            ldsm_x4(am[0], am[1], am[2], am[3], sAm + ro);
#pragma unroll
            for (int ni = 0; ni < 2; ni++) {
                mma16816(acc[mi][ni], ah, bh[ni]);
                mma16816(acc[mi][ni], ah, bm[ni]);
                mma16816(acc[mi][ni], am, bh[ni]);
            }
        }
        __syncthreads();
    }

    // epilogue: bias + write + partial sums
    float lsum = 0.f, lsq = 0.f;
    float* yb = g_y + (size_t)b * CCH * NPOS;
#pragma unroll
    for (int mi = 0; mi < 4; mi++) {
        const int o = wo * 64 + mi * 16 + g;
        const float bo0 = __ldg(&bout[o]);
        const float bo1 = __ldg(&bout[o + 8]);
#pragma unroll
        for (int ni = 0; ni < 2; ni++) {
            const int p = col0 + wp * 16 + ni * 8 + tg * 2;
            float2 v0 = make_float2(acc[mi][ni][0] + bo0, acc[mi][ni][1] + bo0);
            float2 v1 = make_float2(acc[mi][ni][2] + bo1, acc[mi][ni][3] + bo1);
            *(float2*)&yb[(size_t)o * NPOS + p] = v0;
            *(float2*)&yb[(size_t)(o + 8) * NPOS + p] = v1;
            lsum += v0.x + v0.y + v1.x + v1.y;
            lsq  += v0.x * v0.x + v0.y * v0.y + v1.x * v1.x + v1.y * v1.y;
        }
    }
    float* rs = sq;        // sq is dead now
    float* rq = sq + 8;
#pragma unroll
    for (int o = 16; o > 0; o >>= 1) {
        lsum += __shfl_xor_sync(0xffffffffu, lsum, o);
        lsq  += __shfl_xor_sync(0xffffffffu, lsq, o);
    }
    if ((t & 31) == 0) { rs[t >> 5] = lsum; rq[t >> 5] = lsq; }
    __syncthreads();
    if (t == 0) {
        float a = 0.f, q = 0.f;
        for (int i = 0; i < 8; i++) { a += rs[i]; q += rq[i]; }
        g_part[(b * 128 + tile) * 2 + 0] = a;
        g_part[(b * 128 + tile) * 2 + 1] = q;
    }
}

// ---------------------------------------------------------------------------
// K5: combine partials per batch (double precision)
// ---------------------------------------------------------------------------
__global__ void k_gn_stats() {
    const int b = blockIdx.x;
    const int t = threadIdx.x;    // 128
    double s = (double)g_part[(b * 128 + t) * 2 + 0];
    double q = (double)g_part[(b * 128 + t) * 2 + 1];
#pragma unroll
    for (int o = 16; o > 0; o >>= 1) {
        s += __shfl_xor_sync(0xffffffffu, s, o);
        q += __shfl_xor_sync(0xffffffffu, q, o);
    }
    __shared__ double ss[4], qq[4];
    if ((t & 31) == 0) { ss[t >> 5] = s; qq[t >> 5] = q; }
    __syncthreads();
    if (t == 0) {
        double S = 0.0, Q = 0.0;
        for (int i = 0; i < 4; i++) { S += ss[i]; Q += qq[i]; }
        const double cnt = (double)CCH * (double)NPOS;
        const double mean = S / cnt;
        const double var = Q / cnt - mean * mean;
        g_mean[b] = (float)mean;
        g_rstd[b] = (float)(1.0 / sqrt(var + (double)EPSV));
    }
}

// ---------------------------------------------------------------------------
// K6: normalize + gamma/beta
// ---------------------------------------------------------------------------
__global__ __launch_bounds__(256) void k_norm(float* __restrict__ out,
                                              const float* __restrict__ gamma,
                                              const float* __restrict__ beta) {
    const size_t idx4 = (size_t)blockIdx.x * 256 + threadIdx.x;
    const size_t base = idx4 * 4;
    const int b = (int)(base / ((size_t)CCH * NPOS));
    const int c = (int)(base / NPOS) & 255;
    const float mean = g_mean[b], rstd = g_rstd[b];
    const float g = gamma[c] * rstd, bt = beta[c];
    float4 v = *(float4*)&g_y[base];
    v.x = (v.x - mean) * g + bt;
    v.y = (v.y - mean) * g + bt;
    v.z = (v.z - mean) * g + bt;
    v.w = (v.w - mean) * g + bt;
    *(float4*)&out[base] = v;
}

// ---------------------------------------------------------------------------
extern "C" void kernel_launch(void* const* d_in, const int* in_sizes, int n_in,
                              void* d_out, int out_size) {
    const float* x     = (const float*)d_in[0];
    const float* wqkv  = (const float*)d_in[1];
    const float* wout  = (const float*)d_in[2];
    const float* bout  = (const float*)d_in[3];
    const float* gamma = (const float*)d_in[4];
    const float* beta  = (const float*)d_in[5];
    float* out = (float*)d_out;

    cudaFuncSetAttribute(k_qkv_mma, cudaFuncAttributeMaxDynamicSharedMemorySize,
                         SMEM_K1);
    cudaFuncSetAttribute(k_attn_out, cudaFuncAttributeMaxDynamicSharedMemorySize,
                         K4_SMEM);

    k_convw    <<<OC3, 256>>>(wqkv);
    k_convw2   <<<128, 256>>>(wout);
    k_convx    <<<dim3(NPOS / 32, CCH / 32, BATCH), dim3(32, 8)>>>(x);
    k_qkv_mma  <<<dim3(OC3 / 128, NPOS / 128, BATCH), 256, SMEM_K1>>>();
    k_kstats   <<<BATCH * INNER, 256>>>();
    k_context  <<<dim3(NSPLIT, HEADS, BATCH), 256>>>();
    k_ctx_reduce<<<(BATCH * HEADS * DHEAD * DHEAD) / 256, 256>>>();
    k_attn_out <<<dim3(NPOS / 32, BATCH), 256, K4_SMEM>>>(bout);
    k_gn_stats <<<BATCH, 128>>>();
    k_norm     <<<(size_t)BATCH * CCH * NPOS / 4 / 256, 256>>>(out, gamma, beta);
}

// round 5
// speedup vs baseline: 1.4323x; 1.0389x over previous
#include <cuda_runtime.h>
#include <cuda_bf16.h>
#include <math.h>
#include <stdint.h>

// Problem constants
#define BATCH 16
#define CCH   256          // channels
#define NPOS  4096         // 64*64 spatial
#define HEADS 4
#define DHEAD 32
#define INNER 128          // HEADS*DHEAD
#define OC3   384          // 3*INNER
#define SCALEQ 0.17677669529663687f   // 32^-0.5
#define EPSV  1e-5f
#define NSPLIT 8

// ---------------- scratch (static device globals: alloc-free rule) ----------
__device__ float g_qkv[(size_t)BATCH * OC3 * NPOS];          // ~100 MB
__device__ float g_y[(size_t)BATCH * CCH * NPOS];            // ~67 MB
__device__ float g_kmax[BATCH * INNER];
__device__ float g_kinv[BATCH * INNER];
__device__ float g_ctxp[(size_t)BATCH * HEADS * NSPLIT * DHEAD * DHEAD];
__device__ float g_ctx[(size_t)BATCH * HEADS * DHEAD * DHEAD];
__device__ float g_part[BATCH * 128 * 2];                    // per-tile sum / sumsq
__device__ float g_mean[BATCH];
__device__ float g_rstd[BATCH];
// bf16 hi/mid splits: x transposed to [b][p][c]; w kept [o][c]
__device__ __align__(256) __nv_bfloat16 g_xh[(size_t)BATCH * NPOS * CCH];
__device__ __align__(256) __nv_bfloat16 g_xm[(size_t)BATCH * NPOS * CCH];
__device__ __align__(256) __nv_bfloat16 g_wh[OC3 * CCH];
__device__ __align__(256) __nv_bfloat16 g_wm[OC3 * CCH];
__device__ __align__(256) __nv_bfloat16 g_w2h[CCH * INNER];  // w_out split
__device__ __align__(256) __nv_bfloat16 g_w2m[CCH * INNER];

// ---------------------------------------------------------------------------
// mma / ldmatrix / cp.async helpers (portable sm_80+ ISA)
// ---------------------------------------------------------------------------
__device__ __forceinline__ void mma16816(float* c, const uint32_t* a,
                                         const uint32_t* b) {
    asm volatile(
        "mma.sync.aligned.m16n8k16.row.col.f32.bf16.bf16.f32 "
        "{%0,%1,%2,%3}, {%4,%5,%6,%7}, {%8,%9}, {%0,%1,%2,%3};"
        : "+f"(c[0]), "+f"(c[1]), "+f"(c[2]), "+f"(c[3])
        : "r"(a[0]), "r"(a[1]), "r"(a[2]), "r"(a[3]), "r"(b[0]), "r"(b[1]));
}
__device__ __forceinline__ uint32_t sm_addr(const void* p) {
    uint32_t a;
    asm("{ .reg .u64 t; cvta.to.shared.u64 t, %1; cvt.u32.u64 %0, t; }"
        : "=r"(a) : "l"(p));
    return a;
}
__device__ __forceinline__ void ldsm_x4(uint32_t& r0, uint32_t& r1,
                                        uint32_t& r2, uint32_t& r3, uint32_t a) {
    asm volatile("ldmatrix.sync.aligned.m8n8.x4.shared.b16 {%0,%1,%2,%3}, [%4];"
                 : "=r"(r0), "=r"(r1), "=r"(r2), "=r"(r3) : "r"(a));
}
__device__ __forceinline__ void cp16(uint32_t s, const void* g) {
    asm volatile("cp.async.cg.shared.global [%0], [%1], 16;" :: "r"(s), "l"(g));
}
__device__ __forceinline__ void cp_commit() {
    asm volatile("cp.async.commit_group;");
}
template <int N>
__device__ __forceinline__ void cp_wait() {
    asm volatile("cp.async.wait_group %0;" :: "n"(N));
}

// ---------------------------------------------------------------------------
// conv kernels: fp32 -> (hi, mid) bf16 split
// ---------------------------------------------------------------------------
__global__ __launch_bounds__(256) void k_convw(const float* __restrict__ w) {
    const int idx = blockIdx.x * 256 + threadIdx.x;     // OC3*CCH = 98304
    float v = w[idx];
    __nv_bfloat16 h = __float2bfloat16(v);
    g_wh[idx] = h;
    g_wm[idx] = __float2bfloat16(v - __bfloat162float(h));
}
__global__ __launch_bounds__(256) void k_convw2(const float* __restrict__ w) {
    const int idx = blockIdx.x * 256 + threadIdx.x;     // CCH*INNER = 32768
    float v = w[idx];
    __nv_bfloat16 h = __float2bfloat16(v);
    g_w2h[idx] = h;
    g_w2m[idx] = __float2bfloat16(v - __bfloat162float(h));
}

// x[b][c][p] fp32  ->  g_xh/g_xm[b][p][c] bf16 (transposed)
__global__ __launch_bounds__(256) void k_convx(const float* __restrict__ x) {
    __shared__ float tile[32][33];
    const int pt = blockIdx.x, ct = blockIdx.y, b = blockIdx.z;
    const int tx = threadIdx.x, ty = threadIdx.y;       // 32 x 8
    const float* xb = x + ((size_t)b * CCH + ct * 32) * NPOS + pt * 32;
#pragma unroll
    for (int j = 0; j < 4; j++)
        tile[ty + j * 8][tx] = xb[(size_t)(ty + j * 8) * NPOS + tx];
    __syncthreads();
    __nv_bfloat16* oh = g_xh + ((size_t)b * NPOS + pt * 32) * CCH + ct * 32;
    __nv_bfloat16* om = g_xm + ((size_t)b * NPOS + pt * 32) * CCH + ct * 32;
#pragma unroll
    for (int j = 0; j < 4; j++) {
        const int pl = ty + j * 8;
        float v = tile[tx][pl];
        __nv_bfloat16 h = __float2bfloat16(v);
        oh[(size_t)pl * CCH + tx] = h;
        om[(size_t)pl * CCH + tx] = __float2bfloat16(v - __bfloat162float(h));
    }
}

// ---------------------------------------------------------------------------
// K1 (mma.sync + ldmatrix + cp.async, 2-stage pipeline):
//   qkv[b][o][p] = sum_c w[o][c]*x[b][c][p]
//   D[m=o(128)][n=p(128)], warp tile 64x32, 3-term bf16 split.
//   K-chunk 32, double-buffered: prefetch kc+1 under compute of kc.
//   smem rows 40 bf16 (80 B): conflict-free stores & ldmatrix.
// ---------------------------------------------------------------------------
#define ASTR2 40
#define ABYTES (128 * ASTR2 * 2)          // 10240 B per array
#define BUFB   (4 * ABYTES)               // 40960 B per stage
#define SMEM_K1 (2 * BUFB)                // 81920 B
#define NCHUNK 8
__global__ __launch_bounds__(256, 2) void k_qkv_mma() {
    extern __shared__ __nv_bfloat16 sm[];
    const int o0 = blockIdx.x * 128, p0 = blockIdx.y * 128, b = blockIdx.z;
    const int t = threadIdx.x, w = t >> 5, l = t & 31;
    const int wm_ = w & 1, wn_ = w >> 1;          // warp tile: 64(o) x 32(p)

    float acc[4][4][4];
#pragma unroll
    for (int i = 0; i < 4; i++)
#pragma unroll
        for (int j = 0; j < 4; j++)
#pragma unroll
            for (int r = 0; r < 4; r++) acc[i][j][r] = 0.f;

    const __nv_bfloat16* gwh = g_wh + (size_t)o0 * CCH;
    const __nv_bfloat16* gwm = g_wm + (size_t)o0 * CCH;
    const __nv_bfloat16* gxh = g_xh + ((size_t)b * NPOS + p0) * CCH;
    const __nv_bfloat16* gxm = g_xm + ((size_t)b * NPOS + p0) * CCH;

    const uint32_t sbase = sm_addr(sm);
    const int lrow = t >> 1;                 // 0..127
    const int lhalf = (t & 1) * 16;          // 0 or 16 bf16
    const uint32_t cp_dst = (uint32_t)(lrow * ASTR2 + lhalf) * 2;
    const size_t   cp_src = (size_t)lrow * CCH + lhalf;

    // ldmatrix lane offset: row = (l&15), colhalf = (l>>4)*8 elements
    const uint32_t lmoff = (uint32_t)((l & 15) * ASTR2 + (l >> 4) * 8) * 2;

    // issue one chunk's loads into stage buffer `buf`
    auto issue = [&](int kc, int buf) {
        const int k0 = kc * 32;
        const uint32_t d = sbase + (uint32_t)buf * BUFB + cp_dst;
        cp16(d + 0 * ABYTES,      gwh + cp_src + k0);
        cp16(d + 0 * ABYTES + 16, gwh + cp_src + k0 + 8);
        cp16(d + 1 * ABYTES,      gwm + cp_src + k0);
        cp16(d + 1 * ABYTES + 16, gwm + cp_src + k0 + 8);
        cp16(d + 2 * ABYTES,      gxh + cp_src + k0);
        cp16(d + 2 * ABYTES + 16, gxh + cp_src + k0 + 8);
        cp16(d + 3 * ABYTES,      gxm + cp_src + k0);
        cp16(d + 3 * ABYTES + 16, gxm + cp_src + k0 + 8);
        cp_commit();
    };

    issue(0, 0);

    for (int kc = 0; kc < NCHUNK; kc++) {
        if (kc + 1 < NCHUNK) {
            issue(kc + 1, (kc + 1) & 1);
            cp_wait<1>();
        } else {
            cp_wait<0>();
        }
        __syncthreads();

        const uint32_t sb = sbase + (uint32_t)(kc & 1) * BUFB;
        const uint32_t sAwh = sb, sAwm = sb + ABYTES;
        const uint32_t sBxh = sb + 2 * ABYTES, sBxm = sb + 3 * ABYTES;

#pragma unroll
        for (int ks = 0; ks < 2; ks++) {
            const uint32_t kboff = (uint32_t)(ks * 16) * 2;
            uint32_t bh[4][2], bm[4][2];
            {
                uint32_t base = sBxh + lmoff + kboff +
                                (uint32_t)(wn_ * 32) * ASTR2 * 2;
                ldsm_x4(bh[0][0], bh[1][0], bh[0][1], bh[1][1], base);
                ldsm_x4(bh[2][0], bh[3][0], bh[2][1], bh[3][1],
                        base + (uint32_t)(16 * ASTR2 * 2));
                base = sBxm + lmoff + kboff + (uint32_t)(wn_ * 32) * ASTR2 * 2;
                ldsm_x4(bm[0][0], bm[1][0], bm[0][1], bm[1][1], base);
                ldsm_x4(bm[2][0], bm[3][0], bm[2][1], bm[3][1],
                        base + (uint32_t)(16 * ASTR2 * 2));
            }
#pragma unroll
            for (int mi = 0; mi < 4; mi++) {
                const uint32_t roff =
                    (uint32_t)((wm_ * 64 + mi * 16) * ASTR2) * 2 + lmoff + kboff;
                uint32_t ah[4], am[4];
                ldsm_x4(ah[0], ah[1], ah[2], ah[3], sAwh + roff);
                ldsm_x4(am[0], am[1], am[2], am[3], sAwm + roff);
#pragma unroll
                for (int ni = 0; ni < 4; ni++) {
                    mma16816(acc[mi][ni], ah, bh[ni]);
                    mma16816(acc[mi][ni], ah, bm[ni]);
                    mma16816(acc[mi][ni], am, bh[ni]);
                }
            }
        }
        __syncthreads();
    }

    // epilogue: D[o][p] -> g_qkv
    const int g = l >> 2, tg = l & 3;
    float* outb = g_qkv + (size_t)b * OC3 * NPOS;
#pragma unroll
    for (int mi = 0; mi < 4; mi++) {
        const int o = o0 + wm_ * 64 + mi * 16 + g;
#pragma unroll
        for (int ni = 0; ni < 4; ni++) {
            const int p = p0 + wn_ * 32 + ni * 8 + tg * 2;
            *(float2*)&outb[(size_t)o * NPOS + p] =
                make_float2(acc[mi][ni][0], acc[mi][ni][1]);
            *(float2*)&outb[(size_t)(o + 8) * NPOS + p] =
                make_float2(acc[mi][ni][2], acc[mi][ni][3]);
        }
    }
}

// ---------------------------------------------------------------------------
// K2: per (b, k-channel) row: max and 1/sum(exp) over n (single global pass)
// ---------------------------------------------------------------------------
__global__ __launch_bounds__(256) void k_kstats() {
    const int row = blockIdx.x;              // 0 .. B*INNER-1
    const int b = row >> 7, kc = row & 127;
    const float* kr = g_qkv + ((size_t)b * OC3 + INNER + kc) * NPOS;
    const int t = threadIdx.x;
    float v[16];
    float m = -1e30f;
#pragma unroll
    for (int i = 0; i < 16; i++) { v[i] = kr[i * 256 + t]; m = fmaxf(m, v[i]); }
    __shared__ float red[8];
#pragma unroll
    for (int o = 16; o > 0; o >>= 1) m = fmaxf(m, __shfl_xor_sync(0xffffffffu, m, o));
    if ((t & 31) == 0) red[t >> 5] = m;
    __syncthreads();
    if (t < 32) {
        float mm = (t < 8) ? red[t] : -1e30f;
#pragma unroll
        for (int o = 16; o > 0; o >>= 1) mm = fmaxf(mm, __shfl_xor_sync(0xffffffffu, mm, o));
        if (t == 0) red[0] = mm;
    }
    __syncthreads();
    m = red[0];
    __syncthreads();
    float s = 0.f;
#pragma unroll
    for (int i = 0; i < 16; i++) s += __expf(v[i] - m);
#pragma unroll
    for (int o = 16; o > 0; o >>= 1) s += __shfl_xor_sync(0xffffffffu, s, o);
    if ((t & 31) == 0) red[t >> 5] = s;
    __syncthreads();
    if (t == 0) {
        float ss = 0.f;
        for (int i = 0; i < 8; i++) ss += red[i];
        g_kmax[row] = m;
        g_kinv[row] = 1.0f / ss;
    }
}

// ---------------------------------------------------------------------------
// K3: split-K context partials
// ---------------------------------------------------------------------------
__global__ __launch_bounds__(256) void k_context() {
    const int s = blockIdx.x, h = blockIdx.y, b = blockIdx.z;
    __shared__ float ks[32 * 129];
    __shared__ float vs[32 * 129];
    __shared__ float smax[32], sinv[32];
    const int t = threadIdx.x;
    const int e = t & 31, dg = t >> 5;
    float acc[4] = {0.f, 0.f, 0.f, 0.f};
    const float* kbase = g_qkv + ((size_t)b * OC3 + INNER + h * DHEAD) * NPOS;
    const float* vbase = g_qkv + ((size_t)b * OC3 + 2 * INNER + h * DHEAD) * NPOS;
    if (t < 32) {
        smax[t] = g_kmax[b * INNER + h * DHEAD + t];
        sinv[t] = g_kinv[b * INNER + h * DHEAD + t];
    }
    __syncthreads();
    for (int tile = 0; tile < 4; tile++) {
        const int n0 = s * 512 + tile * 128;
#pragma unroll
        for (int i = 0; i < 16; i++) {
            int idx = i * 256 + t;
            int d = idx >> 7, nn = idx & 127;
            float kraw = kbase[(size_t)d * NPOS + n0 + nn];
            ks[d * 129 + nn] = __expf(kraw - smax[d]) * sinv[d];
            vs[d * 129 + nn] = vbase[(size_t)d * NPOS + n0 + nn];
        }
        __syncthreads();
        for (int nn = 0; nn < 128; nn++) {
            float vv = vs[e * 129 + nn];
#pragma unroll
            for (int i = 0; i < 4; i++) acc[i] += ks[(dg * 4 + i) * 129 + nn] * vv;
        }
        __syncthreads();
    }
    float* cp = g_ctxp + ((size_t)(b * HEADS + h) * NSPLIT + s) * 1024;
#pragma unroll
    for (int i = 0; i < 4; i++) cp[(dg * 4 + i) * 32 + e] = acc[i];
}

__global__ void k_ctx_reduce() {
    const int idx = blockIdx.x * 256 + threadIdx.x;   // 65536 total
    const int bh = idx >> 10, de = idx & 1023;
    float s = 0.f;
#pragma unroll
    for (int j = 0; j < NSPLIT; j++)
        s += g_ctxp[((size_t)bh * NSPLIT + j) * 1024 + de];
    g_ctx[(size_t)bh * 1024 + de] = s;
}

// ---------------------------------------------------------------------------
// K4: q-softmax -> inner = ctx^T*softq (FFMA, small) -> y = w_out*inner + b
//     out-projection tensor-core (3-term bf16 split, ldmatrix).
// ---------------------------------------------------------------------------
#define K4_SMEM 58368
#define ISTR 136
__global__ __launch_bounds__(256) void k_attn_out(const float* __restrict__ bout) {
    extern __shared__ char sm4[];
    float* sq  = (float*)sm4;
    float* ctx = (float*)(sm4 + 16384);
    __nv_bfloat16* Ah = (__nv_bfloat16*)(sm4 + 16384);
    __nv_bfloat16* Am = (__nv_bfloat16*)(sm4 + 16384 + 12288);
    __nv_bfloat16* iH = (__nv_bfloat16*)(sm4 + 40960);
    __nv_bfloat16* iM = (__nv_bfloat16*)(sm4 + 49664);
    const int tile = blockIdx.x, b = blockIdx.y;
    const int col0 = tile * 32;
    const int t = threadIdx.x, l = t & 31;
    const float* qbase = g_qkv + (size_t)b * OC3 * NPOS;

    // stage 1: load q tile + ctx
#pragma unroll
    for (int i = 0; i < 16; i++) {
        int idx = i * 256 + t;
        int c = idx >> 5, p = idx & 31;
        sq[c * 32 + p] = qbase[(size_t)c * NPOS + col0 + p];
    }
#pragma unroll
    for (int i = 0; i < 16; i++)
        ctx[i * 256 + t] = g_ctx[(size_t)b * 4096 + i * 256 + t];
    __syncthreads();

    // softmax over d per (head, p) column, * SCALE
    if (t < 128) {
        const int hh = t >> 5, p = t & 31;
        float m = -1e30f;
#pragma unroll
        for (int d = 0; d < 32; d++) m = fmaxf(m, sq[(hh * 32 + d) * 32 + p]);
        float ssum = 0.f;
#pragma unroll
        for (int d = 0; d < 32; d++) ssum += __expf(sq[(hh * 32 + d) * 32 + p] - m);
        const float inv = SCALEQ / ssum;
#pragma unroll
        for (int d = 0; d < 32; d++)
            sq[(hh * 32 + d) * 32 + p] = __expf(sq[(hh * 32 + d) * 32 + p] - m) * inv;
    }
    __syncthreads();

    // stage 2: inner[e][p] = sum_d ctx[hh][d][e]*softq -> write [p][e] bf16 split
    {
        const int p = t & 31, eg = t >> 5;
        const int hh = eg >> 1;
        const int e0 = (eg & 1) * 16;
        float sqv[32];
#pragma unroll
        for (int d = 0; d < 32; d++) sqv[d] = sq[(hh * 32 + d) * 32 + p];
        float acc2[16];
#pragma unroll
        for (int i = 0; i < 16; i++) acc2[i] = 0.f;
#pragma unroll
        for (int d = 0; d < 32; d++) {
            const float qd = sqv[d];
#pragma unroll
            for (int i4 = 0; i4 < 4; i4++) {
                float4 c4 = *(float4*)&ctx[hh * 1024 + d * 32 + e0 + i4 * 4];
                acc2[i4 * 4 + 0] += c4.x * qd;
                acc2[i4 * 4 + 1] += c4.y * qd;
                acc2[i4 * 4 + 2] += c4.z * qd;
                acc2[i4 * 4 + 3] += c4.w * qd;
            }
        }
#pragma unroll
        for (int i = 0; i < 16; i++) {
            float v = acc2[i];
            __nv_bfloat16 h = __float2bfloat16(v);
            iH[p * ISTR + hh * 32 + e0 + i] = h;
            iM[p * ISTR + hh * 32 + e0 + i] =
                __float2bfloat16(v - __bfloat162float(h));
        }
    }
    __syncthreads();   // inner done; ctx area reused for A chunks

    // stage 3 (mma): y[o][p] = sum_e w_out[o][e]*inner[e][p]
    const int wid = t >> 5, wo = wid >> 1, wp = wid & 1;  // warp tile 64o x 16p
    const int g = l >> 2, tg = l & 3;
    float acc[4][2][4];
#pragma unroll
    for (int i = 0; i < 4; i++)
#pragma unroll
        for (int j = 0; j < 2; j++)
#pragma unroll
            for (int r = 0; r < 4; r++) acc[i][j][r] = 0.f;

    const uint32_t sAh = sm_addr(Ah), sAm = sm_addr(Am);
    const uint32_t siH = sm_addr(iH), siM = sm_addr(iM);
    const uint32_t lmrow = (uint32_t)(l & 15);
    const uint32_t lmc8b = (uint32_t)((l >> 4) * 8) * 2;

    for (int ec = 0; ec < 8; ec++) {
        // stage w_out chunk [256o][16e] hi+mid; row stride 24 bf16 (48 B)
        {
            const int o = t;
            uint4 v0 = *(const uint4*)&g_w2h[o * INNER + ec * 16];
            uint4 v1 = *(const uint4*)&g_w2h[o * INNER + ec * 16 + 8];
            *(uint4*)&Ah[o * 24 + 0] = v0;
            *(uint4*)&Ah[o * 24 + 8] = v1;
            uint4 m0 = *(const uint4*)&g_w2m[o * INNER + ec * 16];
            uint4 m1 = *(const uint4*)&g_w2m[o * INNER + ec * 16 + 8];
            *(uint4*)&Am[o * 24 + 0] = m0;
            *(uint4*)&Am[o * 24 + 8] = m1;
        }
        __syncthreads();

        uint32_t bh[2][2], bm[2][2];
        {
            uint32_t base = (uint32_t)((wp * 16 + lmrow) * ISTR + ec * 16) * 2 + lmc8b;
            ldsm_x4(bh[0][0], bh[1][0], bh[0][1], bh[1][1], siH + base);
            ldsm_x4(bm[0][0], bm[1][0], bm[0][1], bm[1][1], siM + base);
        }
#pragma unroll
        for (int mi = 0; mi < 4; mi++) {
            const uint32_t ro = (uint32_t)((wo * 64 + mi * 16 + lmrow) * 24) * 2 + lmc8b;
            uint32_t ah[4], am[4];
            ldsm_x4(ah[0], ah[1], ah[2], ah[3], sAh + ro);
            ldsm_x4(am[0], am[1], am[2], am[3], sAm + ro);
#pragma unroll
            for (int ni = 0; ni < 2; ni++) {
                mma16816(acc[mi][ni], ah, bh[ni]);
                mma16816(acc[mi][ni], ah, bm[ni]);
                mma16816(acc[mi][ni], am, bh[ni]);
            }
        }
        __syncthreads();
    }

    // epilogue: bias + write + partial sums
    float lsum = 0.f, lsq = 0.f;
    float* yb = g_y + (size_t)b * CCH * NPOS;
#pragma unroll
    for (int mi = 0; mi < 4; mi++) {
        const int o = wo * 64 + mi * 16 + g;
        const float bo0 = __ldg(&bout[o]);
        const float bo1 = __ldg(&bout[o + 8]);
#pragma unroll
        for (int ni = 0; ni < 2; ni++) {
            const int p = col0 + wp * 16 + ni * 8 + tg * 2;
            float2 v0 = make_float2(acc[mi][ni][0] + bo0, acc[mi][ni][1] + bo0);
            float2 v1 = make_float2(acc[mi][ni][2] + bo1, acc[mi][ni][3] + bo1);
            *(float2*)&yb[(size_t)o * NPOS + p] = v0;
            *(float2*)&yb[(size_t)(o + 8) * NPOS + p] = v1;
            lsum += v0.x + v0.y + v1.x + v1.y;
            lsq  += v0.x * v0.x + v0.y * v0.y + v1.x * v1.x + v1.y * v1.y;
        }
    }
    float* rs = sq;        // sq is dead now
    float* rq = sq + 8;
#pragma unroll
    for (int o = 16; o > 0; o >>= 1) {
        lsum += __shfl_xor_sync(0xffffffffu, lsum, o);
        lsq  += __shfl_xor_sync(0xffffffffu, lsq, o);
    }
    if ((t & 31) == 0) { rs[t >> 5] = lsum; rq[t >> 5] = lsq; }
    __syncthreads();
    if (t == 0) {
        float a = 0.f, q = 0.f;
        for (int i = 0; i < 8; i++) { a += rs[i]; q += rq[i]; }
        g_part[(b * 128 + tile) * 2 + 0] = a;
        g_part[(b * 128 + tile) * 2 + 1] = q;
    }
}

// ---------------------------------------------------------------------------
// K5: combine partials per batch (double precision)
// ---------------------------------------------------------------------------
__global__ void k_gn_stats() {
    const int b = blockIdx.x;
    const int t = threadIdx.x;    // 128
    double s = (double)g_part[(b * 128 + t) * 2 + 0];
    double q = (double)g_part[(b * 128 + t) * 2 + 1];
#pragma unroll
    for (int o = 16; o > 0; o >>= 1) {
        s += __shfl_xor_sync(0xffffffffu, s, o);
        q += __shfl_xor_sync(0xffffffffu, q, o);
    }
    __shared__ double ss[4], qq[4];
    if ((t & 31) == 0) { ss[t >> 5] = s; qq[t >> 5] = q; }
    __syncthreads();
    if (t == 0) {
        double S = 0.0, Q = 0.0;
        for (int i = 0; i < 4; i++) { S += ss[i]; Q += qq[i]; }
        const double cnt = (double)CCH * (double)NPOS;
        const double mean = S / cnt;
        const double var = Q / cnt - mean * mean;
        g_mean[b] = (float)mean;
        g_rstd[b] = (float)(1.0 / sqrt(var + (double)EPSV));
    }
}

// ---------------------------------------------------------------------------
// K6: normalize + gamma/beta
// ---------------------------------------------------------------------------
__global__ __launch_bounds__(256) void k_norm(float* __restrict__ out,
                                              const float* __restrict__ gamma,
                                              const float* __restrict__ beta) {
    const size_t idx4 = (size_t)blockIdx.x * 256 + threadIdx.x;
    const size_t base = idx4 * 4;
    const int b = (int)(base / ((size_t)CCH * NPOS));
    const int c = (int)(base / NPOS) & 255;
    const float mean = g_mean[b], rstd = g_rstd[b];
    const float g = gamma[c] * rstd, bt = beta[c];
    float4 v = *(float4*)&g_y[base];
    v.x = (v.x - mean) * g + bt;
    v.y = (v.y - mean) * g + bt;
    v.z = (v.z - mean) * g + bt;
    v.w = (v.w - mean) * g + bt;
    *(float4*)&out[base] = v;
}

// ---------------------------------------------------------------------------
extern "C" void kernel_launch(void* const* d_in, const int* in_sizes, int n_in,
                              void* d_out, int out_size) {
    const float* x     = (const float*)d_in[0];
    const float* wqkv  = (const float*)d_in[1];
    const float* wout  = (const float*)d_in[2];
    const float* bout  = (const float*)d_in[3];
    const float* gamma = (const float*)d_in[4];
    const float* beta  = (const float*)d_in[5];
    float* out = (float*)d_out;

    cudaFuncSetAttribute(k_qkv_mma, cudaFuncAttributeMaxDynamicSharedMemorySize,
                         SMEM_K1);
    cudaFuncSetAttribute(k_attn_out, cudaFuncAttributeMaxDynamicSharedMemorySize,
                         K4_SMEM);

    k_convw    <<<OC3, 256>>>(wqkv);
    k_convw2   <<<128, 256>>>(wout);
    k_convx    <<<dim3(NPOS / 32, CCH / 32, BATCH), dim3(32, 8)>>>(x);
    k_qkv_mma  <<<dim3(OC3 / 128, NPOS / 128, BATCH), 256, SMEM_K1>>>();
    k_kstats   <<<BATCH * INNER, 256>>>();
    k_context  <<<dim3(NSPLIT, HEADS, BATCH), 256>>>();
    k_ctx_reduce<<<(BATCH * HEADS * DHEAD * DHEAD) / 256, 256>>>();
    k_attn_out <<<dim3(NPOS / 32, BATCH), 256, K4_SMEM>>>(bout);
    k_gn_stats <<<BATCH, 128>>>();
    k_norm     <<<(size_t)BATCH * CCH * NPOS / 4 / 256, 256>>>(out, gamma, beta);
}

// round 8
// speedup vs baseline: 1.4970x; 1.0452x over previous
#include <cuda_runtime.h>
#include <cuda_bf16.h>
#include <math.h>
#include <stdint.h>

// Problem constants
#define BATCH 16
#define CCH   256          // channels
#define NPOS  4096         // 64*64 spatial
#define HEADS 4
#define DHEAD 32
#define INNER 128          // HEADS*DHEAD
#define OC3   384          // 3*INNER
#define SCALEQ 0.17677669529663687f   // 32^-0.5
#define EPSV  1e-5f
#define NSPLIT 8

// ---------------- scratch (static device globals: alloc-free rule) ----------
__device__ float g_qkv[(size_t)BATCH * OC3 * NPOS];          // ~100 MB
__device__ float g_y[(size_t)BATCH * CCH * NPOS];            // ~67 MB
__device__ float g_kmax[BATCH * INNER];
__device__ float g_kinv[BATCH * INNER];
__device__ float g_ctxp[(size_t)BATCH * HEADS * NSPLIT * DHEAD * DHEAD];
__device__ float g_ctx[(size_t)BATCH * HEADS * DHEAD * DHEAD];
__device__ float g_part[BATCH * 64 * 2];                     // per-tile sum / sumsq
__device__ float g_mean[BATCH];
__device__ float g_rstd[BATCH];
// bf16 hi/mid splits: x transposed to [b][p][c]; w kept [o][c]
__device__ __align__(256) __nv_bfloat16 g_xh[(size_t)BATCH * NPOS * CCH];
__device__ __align__(256) __nv_bfloat16 g_xm[(size_t)BATCH * NPOS * CCH];
__device__ __align__(256) __nv_bfloat16 g_wh[OC3 * CCH];
__device__ __align__(256) __nv_bfloat16 g_wm[OC3 * CCH];
__device__ __align__(256) __nv_bfloat16 g_w2h[CCH * INNER];  // w_out split
__device__ __align__(256) __nv_bfloat16 g_w2m[CCH * INNER];

// ---------------------------------------------------------------------------
// mma / ldmatrix / cp.async helpers (portable sm_80+ ISA)
// ---------------------------------------------------------------------------
__device__ __forceinline__ void mma16816(float* c, const uint32_t* a,
                                         const uint32_t* b) {
    asm volatile(
        "mma.sync.aligned.m16n8k16.row.col.f32.bf16.bf16.f32 "
        "{%0,%1,%2,%3}, {%4,%5,%6,%7}, {%8,%9}, {%0,%1,%2,%3};"
        : "+f"(c[0]), "+f"(c[1]), "+f"(c[2]), "+f"(c[3])
        : "r"(a[0]), "r"(a[1]), "r"(a[2]), "r"(a[3]), "r"(b[0]), "r"(b[1]));
}
__device__ __forceinline__ uint32_t sm_addr(const void* p) {
    uint32_t a;
    asm("{ .reg .u64 t; cvta.to.shared.u64 t, %1; cvt.u32.u64 %0, t; }"
        : "=r"(a) : "l"(p));
    return a;
}
__device__ __forceinline__ void ldsm_x4(uint32_t& r0, uint32_t& r1,
                                        uint32_t& r2, uint32_t& r3, uint32_t a) {
    asm volatile("ldmatrix.sync.aligned.m8n8.x4.shared.b16 {%0,%1,%2,%3}, [%4];"
                 : "=r"(r0), "=r"(r1), "=r"(r2), "=r"(r3) : "r"(a));
}
__device__ __forceinline__ void cp16(uint32_t s, const void* g) {
    asm volatile("cp.async.cg.shared.global [%0], [%1], 16;" :: "r"(s), "l"(g));
}
__device__ __forceinline__ void cp_commit() {
    asm volatile("cp.async.commit_group;");
}
template <int N>
__device__ __forceinline__ void cp_wait() {
    asm volatile("cp.async.wait_group %0;" :: "n"(N));
}

// ---------------------------------------------------------------------------
// conv kernels: fp32 -> (hi, mid) bf16 split
// ---------------------------------------------------------------------------
__global__ __launch_bounds__(256) void k_convw(const float* __restrict__ w) {
    const int idx = blockIdx.x * 256 + threadIdx.x;     // OC3*CCH = 98304
    float v = w[idx];
    __nv_bfloat16 h = __float2bfloat16(v);
    g_wh[idx] = h;
    g_wm[idx] = __float2bfloat16(v - __bfloat162float(h));
}
__global__ __launch_bounds__(256) void k_convw2(const float* __restrict__ w) {
    const int idx = blockIdx.x * 256 + threadIdx.x;     // CCH*INNER = 32768
    float v = w[idx];
    __nv_bfloat16 h = __float2bfloat16(v);
    g_w2h[idx] = h;
    g_w2m[idx] = __float2bfloat16(v - __bfloat162float(h));
}

// x[b][c][p] fp32  ->  g_xh/g_xm[b][p][c] bf16 (transposed)
__global__ __launch_bounds__(256) void k_convx(const float* __restrict__ x) {
    __shared__ float tile[32][33];
    const int pt = blockIdx.x, ct = blockIdx.y, b = blockIdx.z;
    const int tx = threadIdx.x, ty = threadIdx.y;       // 32 x 8
    const float* xb = x + ((size_t)b * CCH + ct * 32) * NPOS + pt * 32;
#pragma unroll
    for (int j = 0; j < 4; j++)
        tile[ty + j * 8][tx] = xb[(size_t)(ty + j * 8) * NPOS + tx];
    __syncthreads();
    __nv_bfloat16* oh = g_xh + ((size_t)b * NPOS + pt * 32) * CCH + ct * 32;
    __nv_bfloat16* om = g_xm + ((size_t)b * NPOS + pt * 32) * CCH + ct * 32;
#pragma unroll
    for (int j = 0; j < 4; j++) {
        const int pl = ty + j * 8;
        float v = tile[tx][pl];
        __nv_bfloat16 h = __float2bfloat16(v);
        oh[(size_t)pl * CCH + tx] = h;
        om[(size_t)pl * CCH + tx] = __float2bfloat16(v - __bfloat162float(h));
    }
}

// ---------------------------------------------------------------------------
// K1 (mma.sync + ldmatrix + cp.async, 2-stage pipeline) — round-5 proven
//   qkv[b][o][p] = sum_c w[o][c]*x[b][c][p]
//   D[m=o(128)][n=p(128)], warp tile 64x32, 3-term bf16 split.
//   K-chunk 32, double-buffered: prefetch kc+1 under compute of kc.
// ---------------------------------------------------------------------------
#define ASTR2 40
#define ABYTES (128 * ASTR2 * 2)          // 10240 B per array
#define BUFB   (4 * ABYTES)               // 40960 B per stage
#define SMEM_K1 (2 * BUFB)                // 81920 B
#define NCHUNK 8
__global__ __launch_bounds__(256, 2) void k_qkv_mma() {
    extern __shared__ __nv_bfloat16 sm[];
    const int o0 = blockIdx.x * 128, p0 = blockIdx.y * 128, b = blockIdx.z;
    const int t = threadIdx.x, w = t >> 5, l = t & 31;
    const int wm_ = w & 1, wn_ = w >> 1;          // warp tile: 64(o) x 32(p)

    float acc[4][4][4];
#pragma unroll
    for (int i = 0; i < 4; i++)
#pragma unroll
        for (int j = 0; j < 4; j++)
#pragma unroll
            for (int r = 0; r < 4; r++) acc[i][j][r] = 0.f;

    const __nv_bfloat16* gwh = g_wh + (size_t)o0 * CCH;
    const __nv_bfloat16* gwm = g_wm + (size_t)o0 * CCH;
    const __nv_bfloat16* gxh = g_xh + ((size_t)b * NPOS + p0) * CCH;
    const __nv_bfloat16* gxm = g_xm + ((size_t)b * NPOS + p0) * CCH;

    const uint32_t sbase = sm_addr(sm);
    const int lrow = t >> 1;                 // 0..127
    const int lhalf = (t & 1) * 16;          // 0 or 16 bf16
    const uint32_t cp_dst = (uint32_t)(lrow * ASTR2 + lhalf) * 2;
    const size_t   cp_src = (size_t)lrow * CCH + lhalf;

    // ldmatrix lane offset: row = (l&15), colhalf = (l>>4)*8 elements
    const uint32_t lmoff = (uint32_t)((l & 15) * ASTR2 + (l >> 4) * 8) * 2;

    auto issue = [&](int kc, int buf) {
        const int k0 = kc * 32;
        const uint32_t d = sbase + (uint32_t)buf * BUFB + cp_dst;
        cp16(d + 0 * ABYTES,      gwh + cp_src + k0);
        cp16(d + 0 * ABYTES + 16, gwh + cp_src + k0 + 8);
        cp16(d + 1 * ABYTES,      gwm + cp_src + k0);
        cp16(d + 1 * ABYTES + 16, gwm + cp_src + k0 + 8);
        cp16(d + 2 * ABYTES,      gxh + cp_src + k0);
        cp16(d + 2 * ABYTES + 16, gxh + cp_src + k0 + 8);
        cp16(d + 3 * ABYTES,      gxm + cp_src + k0);
        cp16(d + 3 * ABYTES + 16, gxm + cp_src + k0 + 8);
        cp_commit();
    };

    issue(0, 0);

    for (int kc = 0; kc < NCHUNK; kc++) {
        if (kc + 1 < NCHUNK) {
            issue(kc + 1, (kc + 1) & 1);
            cp_wait<1>();
        } else {
            cp_wait<0>();
        }
        __syncthreads();

        const uint32_t sb = sbase + (uint32_t)(kc & 1) * BUFB;
        const uint32_t sAwh = sb, sAwm = sb + ABYTES;
        const uint32_t sBxh = sb + 2 * ABYTES, sBxm = sb + 3 * ABYTES;

#pragma unroll
        for (int ks = 0; ks < 2; ks++) {
            const uint32_t kboff = (uint32_t)(ks * 16) * 2;
            uint32_t bh[4][2], bm[4][2];
            {
                uint32_t base = sBxh + lmoff + kboff +
                                (uint32_t)(wn_ * 32) * ASTR2 * 2;
                ldsm_x4(bh[0][0], bh[1][0], bh[0][1], bh[1][1], base);
                ldsm_x4(bh[2][0], bh[3][0], bh[2][1], bh[3][1],
                        base + (uint32_t)(16 * ASTR2 * 2));
                base = sBxm + lmoff + kboff + (uint32_t)(wn_ * 32) * ASTR2 * 2;
                ldsm_x4(bm[0][0], bm[1][0], bm[0][1], bm[1][1], base);
                ldsm_x4(bm[2][0], bm[3][0], bm[2][1], bm[3][1],
                        base + (uint32_t)(16 * ASTR2 * 2));
            }
#pragma unroll
            for (int mi = 0; mi < 4; mi++) {
                const uint32_t roff =
                    (uint32_t)((wm_ * 64 + mi * 16) * ASTR2) * 2 + lmoff + kboff;
                uint32_t ah[4], am[4];
                ldsm_x4(ah[0], ah[1], ah[2], ah[3], sAwh + roff);
                ldsm_x4(am[0], am[1], am[2], am[3], sAwm + roff);
#pragma unroll
                for (int ni = 0; ni < 4; ni++) {
                    mma16816(acc[mi][ni], ah, bh[ni]);
                    mma16816(acc[mi][ni], ah, bm[ni]);
                    mma16816(acc[mi][ni], am, bh[ni]);
                }
            }
        }
        __syncthreads();
    }

    // epilogue: D[o][p] -> g_qkv
    const int g = l >> 2, tg = l & 3;
    float* outb = g_qkv + (size_t)b * OC3 * NPOS;
#pragma unroll
    for (int mi = 0; mi < 4; mi++) {
        const int o = o0 + wm_ * 64 + mi * 16 + g;
#pragma unroll
        for (int ni = 0; ni < 4; ni++) {
            const int p = p0 + wn_ * 32 + ni * 8 + tg * 2;
            *(float2*)&outb[(size_t)o * NPOS + p] =
                make_float2(acc[mi][ni][0], acc[mi][ni][1]);
            *(float2*)&outb[(size_t)(o + 8) * NPOS + p] =
                make_float2(acc[mi][ni][2], acc[mi][ni][3]);
        }
    }
}

// ---------------------------------------------------------------------------
// K2: per (b, k-channel) row: max and 1/sum(exp) over n (single global pass)
// ---------------------------------------------------------------------------
__global__ __launch_bounds__(256) void k_kstats() {
    const int row = blockIdx.x;              // 0 .. B*INNER-1
    const int b = row >> 7, kc = row & 127;
    const float* kr = g_qkv + ((size_t)b * OC3 + INNER + kc) * NPOS;
    const int t = threadIdx.x;
    float v[16];
    float m = -1e30f;
#pragma unroll
    for (int i = 0; i < 16; i++) { v[i] = kr[i * 256 + t]; m = fmaxf(m, v[i]); }
    __shared__ float red[8];
#pragma unroll
    for (int o = 16; o > 0; o >>= 1) m = fmaxf(m, __shfl_xor_sync(0xffffffffu, m, o));
    if ((t & 31) == 0) red[t >> 5] = m;
    __syncthreads();
    if (t < 32) {
        float mm = (t < 8) ? red[t] : -1e30f;
#pragma unroll
        for (int o = 16; o > 0; o >>= 1) mm = fmaxf(mm, __shfl_xor_sync(0xffffffffu, mm, o));
        if (t == 0) red[0] = mm;
    }
    __syncthreads();
    m = red[0];
    __syncthreads();
    float s = 0.f;
#pragma unroll
    for (int i = 0; i < 16; i++) s += __expf(v[i] - m);
#pragma unroll
    for (int o = 16; o > 0; o >>= 1) s += __shfl_xor_sync(0xffffffffu, s, o);
    if ((t & 31) == 0) red[t >> 5] = s;
    __syncthreads();
    if (t == 0) {
        float ss = 0.f;
        for (int i = 0; i < 8; i++) ss += red[i];
        g_kmax[row] = m;
        g_kinv[row] = 1.0f / ss;
    }
}

// ---------------------------------------------------------------------------
// K3: split-K context partials
// ---------------------------------------------------------------------------
__global__ __launch_bounds__(256) void k_context() {
    const int s = blockIdx.x, h = blockIdx.y, b = blockIdx.z;
    __shared__ float ks[32 * 129];
    __shared__ float vs[32 * 129];
    __shared__ float smax[32], sinv[32];
    const int t = threadIdx.x;
    const int e = t & 31, dg = t >> 5;
    float acc[4] = {0.f, 0.f, 0.f, 0.f};
    const float* kbase = g_qkv + ((size_t)b * OC3 + INNER + h * DHEAD) * NPOS;
    const float* vbase = g_qkv + ((size_t)b * OC3 + 2 * INNER + h * DHEAD) * NPOS;
    if (t < 32) {
        smax[t] = g_kmax[b * INNER + h * DHEAD + t];
        sinv[t] = g_kinv[b * INNER + h * DHEAD + t];
    }
    __syncthreads();
    for (int tile = 0; tile < 4; tile++) {
        const int n0 = s * 512 + tile * 128;
#pragma unroll
        for (int i = 0; i < 16; i++) {
            int idx = i * 256 + t;
            int d = idx >> 7, nn = idx & 127;
            float kraw = kbase[(size_t)d * NPOS + n0 + nn];
            ks[d * 129 + nn] = __expf(kraw - smax[d]) * sinv[d];
            vs[d * 129 + nn] = vbase[(size_t)d * NPOS + n0 + nn];
        }
        __syncthreads();
        for (int nn = 0; nn < 128; nn++) {
            float vv = vs[e * 129 + nn];
#pragma unroll
            for (int i = 0; i < 4; i++) acc[i] += ks[(dg * 4 + i) * 129 + nn] * vv;
        }
        __syncthreads();
    }
    float* cp = g_ctxp + ((size_t)(b * HEADS + h) * NSPLIT + s) * 1024;
#pragma unroll
    for (int i = 0; i < 4; i++) cp[(dg * 4 + i) * 32 + e] = acc[i];
}

__global__ void k_ctx_reduce() {
    const int idx = blockIdx.x * 256 + threadIdx.x;   // 65536 total
    const int bh = idx >> 10, de = idx & 1023;
    float s = 0.f;
#pragma unroll
    for (int j = 0; j < NSPLIT; j++)
        s += g_ctxp[((size_t)bh * NSPLIT + j) * 1024 + de];
    g_ctx[(size_t)bh * 1024 + de] = s;
}

// ---------------------------------------------------------------------------
// K4: q-softmax -> inner = ctx^T*softq -> y = w_out*inner + b   (p-tile = 64)
// smem (bytes):
//   sq  fp32 [128c][64p]         32768   @ 0
//   ctx fp32 [4096] | A hi+mid   24576   @ 32768
//   iH  bf16 [64p][136e]         17408   @ 57344
//   iM  bf16                     17408   @ 74752      total 92160
// ---------------------------------------------------------------------------
#define K4_SMEM 92160
#define ISTR 136
__global__ __launch_bounds__(256) void k_attn_out(const float* __restrict__ bout) {
    extern __shared__ char sm4[];
    float* sq  = (float*)sm4;
    float* ctx = (float*)(sm4 + 32768);
    __nv_bfloat16* Ah = (__nv_bfloat16*)(sm4 + 32768);
    __nv_bfloat16* Am = (__nv_bfloat16*)(sm4 + 32768 + 12288);
    __nv_bfloat16* iH = (__nv_bfloat16*)(sm4 + 57344);
    __nv_bfloat16* iM = (__nv_bfloat16*)(sm4 + 74752);
    const int tile = blockIdx.x, b = blockIdx.y;
    const int col0 = tile * 64;
    const int t = threadIdx.x, l = t & 31;
    const float* qbase = g_qkv + (size_t)b * OC3 * NPOS;

    // stage 1: load q tile [128c][64p] + ctx
#pragma unroll
    for (int i = 0; i < 32; i++) {
        int idx = i * 256 + t;
        int c = idx >> 6, p = idx & 63;
        sq[c * 64 + p] = qbase[(size_t)c * NPOS + col0 + p];
    }
#pragma unroll
    for (int i = 0; i < 16; i++)
        ctx[i * 256 + t] = g_ctx[(size_t)b * 4096 + i * 256 + t];
    __syncthreads();

    // softmax over d per (head, p) column, * SCALE  (all 256 threads)
    {
        const int hh = t >> 6, p = t & 63;
        float m = -1e30f;
#pragma unroll
        for (int d = 0; d < 32; d++) m = fmaxf(m, sq[(hh * 32 + d) * 64 + p]);
        float ssum = 0.f;
#pragma unroll
        for (int d = 0; d < 32; d++) ssum += __expf(sq[(hh * 32 + d) * 64 + p] - m);
        const float inv = SCALEQ / ssum;
#pragma unroll
        for (int d = 0; d < 32; d++)
            sq[(hh * 32 + d) * 64 + p] = __expf(sq[(hh * 32 + d) * 64 + p] - m) * inv;
    }
    __syncthreads();

    // stage 2: inner[e][p] = sum_d ctx[hh][d][e]*softq  -> [p][e] bf16 split
    {
        const int p = t & 63, hh = t >> 6;
        float sqv[32];
#pragma unroll
        for (int d = 0; d < 32; d++) sqv[d] = sq[(hh * 32 + d) * 64 + p];
#pragma unroll
        for (int half = 0; half < 2; half++) {
            const int e0 = half * 16;
            float acc2[16];
#pragma unroll
            for (int i = 0; i < 16; i++) acc2[i] = 0.f;
#pragma unroll
            for (int d = 0; d < 32; d++) {
                const float qd = sqv[d];
#pragma unroll
                for (int i4 = 0; i4 < 4; i4++) {
                    float4 c4 = *(float4*)&ctx[hh * 1024 + d * 32 + e0 + i4 * 4];
                    acc2[i4 * 4 + 0] += c4.x * qd;
                    acc2[i4 * 4 + 1] += c4.y * qd;
                    acc2[i4 * 4 + 2] += c4.z * qd;
                    acc2[i4 * 4 + 3] += c4.w * qd;
                }
            }
#pragma unroll
            for (int i = 0; i < 16; i++) {
                float v = acc2[i];
                __nv_bfloat16 h = __float2bfloat16(v);
                iH[p * ISTR + hh * 32 + e0 + i] = h;
                iM[p * ISTR + hh * 32 + e0 + i] =
                    __float2bfloat16(v - __bfloat162float(h));
            }
        }
    }
    __syncthreads();   // inner done; ctx area reused for A chunks

    // stage 3 (mma): y[o][p] = sum_e w_out[o][e]*inner[e][p]
    const int wid = t >> 5, wo = wid >> 1, wp = wid & 1;  // warp tile 64o x 32p
    const int g = l >> 2, tg = l & 3;
    float acc[4][4][4];
#pragma unroll
    for (int i = 0; i < 4; i++)
#pragma unroll
        for (int j = 0; j < 4; j++)
#pragma unroll
            for (int r = 0; r < 4; r++) acc[i][j][r] = 0.f;

    const uint32_t sAh = sm_addr(Ah), sAm = sm_addr(Am);
    const uint32_t siH = sm_addr(iH), siM = sm_addr(iM);
    const uint32_t lmrow = (uint32_t)(l & 15);
    const uint32_t lmc8b = (uint32_t)((l >> 4) * 8) * 2;

    for (int ec = 0; ec < 8; ec++) {
        // stage w_out chunk [256o][16e] hi+mid; row stride 24 bf16 (48 B)
        {
            const int o = t;
            uint4 v0 = *(const uint4*)&g_w2h[o * INNER + ec * 16];
            uint4 v1 = *(const uint4*)&g_w2h[o * INNER + ec * 16 + 8];
            *(uint4*)&Ah[o * 24 + 0] = v0;
            *(uint4*)&Ah[o * 24 + 8] = v1;
            uint4 m0 = *(const uint4*)&g_w2m[o * INNER + ec * 16];
            uint4 m1 = *(const uint4*)&g_w2m[o * INNER + ec * 16 + 8];
            *(uint4*)&Am[o * 24 + 0] = m0;
            *(uint4*)&Am[o * 24 + 8] = m1;
        }
        __syncthreads();

        uint32_t bh[4][2], bm[4][2];
        {
            uint32_t base = siH +
                (uint32_t)((wp * 32 + lmrow) * ISTR + ec * 16) * 2 + lmc8b;
            ldsm_x4(bh[0][0], bh[1][0], bh[0][1], bh[1][1], base);
            ldsm_x4(bh[2][0], bh[3][0], bh[2][1], bh[3][1],
                    base + (uint32_t)(16 * ISTR) * 2);
            base = siM + (uint32_t)((wp * 32 + lmrow) * ISTR + ec * 16) * 2 + lmc8b;
            ldsm_x4(bm[0][0], bm[1][0], bm[0][1], bm[1][1], base);
            ldsm_x4(bm[2][0], bm[3][0], bm[2][1], bm[3][1],
                    base + (uint32_t)(16 * ISTR) * 2);
        }
#pragma unroll
        for (int mi = 0; mi < 4; mi++) {
            const uint32_t ro = (uint32_t)((wo * 64 + mi * 16 + lmrow) * 24) * 2 + lmc8b;
            uint32_t ah[4], am[4];
            ldsm_x4(ah[0], ah[1], ah[2], ah[3], sAh + ro);
            ldsm_x4(am[0], am[1], am[2], am[3], sAm + ro);
#pragma unroll
            for (int ni = 0; ni < 4; ni++) {
                mma16816(acc[mi][ni], ah, bh[ni]);
                mma16816(acc[mi][ni], ah, bm[ni]);
                mma16816(acc[mi][ni], am, bh[ni]);
            }
        }
        __syncthreads();
    }

    // epilogue: bias + write + partial sums
    float lsum = 0.f, lsq = 0.f;
    float* yb = g_y + (size_t)b * CCH * NPOS;
#pragma unroll
    for (int mi = 0; mi < 4; mi++) {
        const int o = wo * 64 + mi * 16 + g;
        const float bo0 = __ldg(&bout[o]);
        const float bo1 = __ldg(&bout[o + 8]);
#pragma unroll
        for (int ni = 0; ni < 4; ni++) {
            const int p = col0 + wp * 32 + ni * 8 + tg * 2;
            float2 v0 = make_float2(acc[mi][ni][0] + bo0, acc[mi][ni][1] + bo0);
            float2 v1 = make_float2(acc[mi][ni][2] + bo1, acc[mi][ni][3] + bo1);
            *(float2*)&yb[(size_t)o * NPOS + p] = v0;
            *(float2*)&yb[(size_t)(o + 8) * NPOS + p] = v1;
            lsum += v0.x + v0.y + v1.x + v1.y;
            lsq  += v0.x * v0.x + v0.y * v0.y + v1.x * v1.x + v1.y * v1.y;
        }
    }
    float* rs = sq;        // sq is dead now
    float* rq = sq + 8;
#pragma unroll
    for (int o = 16; o > 0; o >>= 1) {
        lsum += __shfl_xor_sync(0xffffffffu, lsum, o);
        lsq  += __shfl_xor_sync(0xffffffffu, lsq, o);
    }
    if ((t & 31) == 0) { rs[t >> 5] = lsum; rq[t >> 5] = lsq; }
    __syncthreads();
    if (t == 0) {
        float a = 0.f, q = 0.f;
        for (int i = 0; i < 8; i++) { a += rs[i]; q += rq[i]; }
        g_part[(b * 64 + tile) * 2 + 0] = a;
        g_part[(b * 64 + tile) * 2 + 1] = q;
    }
}

// ---------------------------------------------------------------------------
// K5: combine partials per batch (double precision), 64 tiles
// ---------------------------------------------------------------------------
__global__ void k_gn_stats() {
    const int b = blockIdx.x;
    const int t = threadIdx.x;    // 64
    double s = (double)g_part[(b * 64 + t) * 2 + 0];
    double q = (double)g_part[(b * 64 + t) * 2 + 1];
#pragma unroll
    for (int o = 16; o > 0; o >>= 1) {
        s += __shfl_xor_sync(0xffffffffu, s, o);
        q += __shfl_xor_sync(0xffffffffu, q, o);
    }
    __shared__ double ss[2], qq[2];
    if ((t & 31) == 0) { ss[t >> 5] = s; qq[t >> 5] = q; }
    __syncthreads();
    if (t == 0) {
        double S = ss[0] + ss[1], Q = qq[0] + qq[1];
        const double cnt = (double)CCH * (double)NPOS;
        const double mean = S / cnt;
        const double var = Q / cnt - mean * mean;
        g_mean[b] = (float)mean;
        g_rstd[b] = (float)(1.0 / sqrt(var + (double)EPSV));
    }
}

// ---------------------------------------------------------------------------
// K6: normalize + gamma/beta
// ---------------------------------------------------------------------------
__global__ __launch_bounds__(256) void k_norm(float* __restrict__ out,
                                              const float* __restrict__ gamma,
                                              const float* __restrict__ beta) {
    const size_t idx4 = (size_t)blockIdx.x * 256 + threadIdx.x;
    const size_t base = idx4 * 4;
    const int b = (int)(base / ((size_t)CCH * NPOS));
    const int c = (int)(base / NPOS) & 255;
    const float mean = g_mean[b], rstd = g_rstd[b];
    const float g = gamma[c] * rstd, bt = beta[c];
    float4 v = *(float4*)&g_y[base];
    v.x = (v.x - mean) * g + bt;
    v.y = (v.y - mean) * g + bt;
    v.z = (v.z - mean) * g + bt;
    v.w = (v.w - mean) * g + bt;
    *(float4*)&out[base] = v;
}

// ---------------------------------------------------------------------------
extern "C" void kernel_launch(void* const* d_in, const int* in_sizes, int n_in,
                              void* d_out, int out_size) {
    const float* x     = (const float*)d_in[0];
    const float* wqkv  = (const float*)d_in[1];
    const float* wout  = (const float*)d_in[2];
    const float* bout  = (const float*)d_in[3];
    const float* gamma = (const float*)d_in[4];
    const float* beta  = (const float*)d_in[5];
    float* out = (float*)d_out;

    cudaFuncSetAttribute(k_qkv_mma, cudaFuncAttributeMaxDynamicSharedMemorySize,
                         SMEM_K1);
    cudaFuncSetAttribute(k_attn_out, cudaFuncAttributeMaxDynamicSharedMemorySize,
                         K4_SMEM);

    k_convw    <<<OC3, 256>>>(wqkv);
    k_convw2   <<<128, 256>>>(wout);
    k_convx    <<<dim3(NPOS / 32, CCH / 32, BATCH), dim3(32, 8)>>>(x);
    k_qkv_mma  <<<dim3(OC3 / 128, NPOS / 128, BATCH), 256, SMEM_K1>>>();
    k_kstats   <<<BATCH * INNER, 256>>>();
    k_context  <<<dim3(NSPLIT, HEADS, BATCH), 256>>>();
    k_ctx_reduce<<<(BATCH * HEADS * DHEAD * DHEAD) / 256, 256>>>();
    k_attn_out <<<dim3(NPOS / 64, BATCH), 256, K4_SMEM>>>(bout);
    k_gn_stats <<<BATCH, 64>>>();
    k_norm     <<<(size_t)BATCH * CCH * NPOS / 4 / 256, 256>>>(out, gamma, beta);
}